// round 1
// baseline (speedup 1.0000x reference)
#include <cuda_runtime.h>
#include <cstddef>

#define NX    2048
#define LY    256
#define HH    24
#define DD    128
#define DXC   3072
#define DYC   1536
#define QKVC  9216
#define TOTALT 2248

// ---------------- scratch (static device globals; no allocation) ------------
__device__ float g_xm  [(size_t)NX * DXC];
__device__ float g_ym  [(size_t)LY * DYC];
__device__ float g_qkvx[(size_t)NX * QKVC];
__device__ float g_qkvy[(size_t)LY * QKVC];
__device__ float g_q   [(size_t)HH * TOTALT * DD];
__device__ float g_k   [(size_t)HH * TOTALT * DD];
__device__ float g_v   [(size_t)HH * TOTALT * DD];
__device__ float g_full[(size_t)(NX + LY) * DXC];

// ---------------- rmsnorm * (1 + scale) ------------------------------------
__global__ void rmsnorm_mod_kernel(const float* __restrict__ x,
                                   const float* __restrict__ scale,
                                   float* __restrict__ out, int C) {
    int row = blockIdx.x;
    const float* xr = x + (size_t)row * C;
    float ss = 0.f;
    for (int c = threadIdx.x; c < C; c += blockDim.x) { float v = xr[c]; ss += v * v; }
    __shared__ float wsum[8];
    #pragma unroll
    for (int o = 16; o > 0; o >>= 1) ss += __shfl_xor_sync(0xffffffffu, ss, o);
    if ((threadIdx.x & 31) == 0) wsum[threadIdx.x >> 5] = ss;
    __syncthreads();
    float tot = 0.f;
    #pragma unroll
    for (int i = 0; i < 8; i++) tot += wsum[i];
    float r = rsqrtf(tot / (float)C + 1e-6f);
    float* orow = out + (size_t)row * C;
    for (int c = threadIdx.x; c < C; c += blockDim.x)
        orow[c] = xr[c] * r * (1.f + scale[c]);
}

// ---------------- zero fill --------------------------------------------------
__global__ void zero_kernel(float* __restrict__ p, int n) {
    for (int i = blockIdx.x * blockDim.x + threadIdx.x; i < n; i += gridDim.x * blockDim.x)
        p[i] = 0.f;
}

// ---------------- tiled fp32 NT GEMM: C[M,N] = A[M,K] * W[N,K]^T + b --------
// BM=BN=128, BK=16, 256 threads, 8x8 microtile. All dims divide exactly.
__global__ void __launch_bounds__(256)
gemm_nt_bias(const float* __restrict__ A, const float* __restrict__ W,
             const float* __restrict__ bias, float* __restrict__ C,
             int M, int N, int K) {
    __shared__ float As[16][136];
    __shared__ float Ws[16][136];
    const int tx = threadIdx.x & 15;
    const int ty = threadIdx.x >> 4;
    const int m0 = blockIdx.y * 128;
    const int n0 = blockIdx.x * 128;
    float acc[8][8];
    #pragma unroll
    for (int i = 0; i < 8; i++)
        #pragma unroll
        for (int j = 0; j < 8; j++) acc[i][j] = 0.f;

    for (int k0 = 0; k0 < K; k0 += 16) {
        #pragma unroll
        for (int r = 0; r < 2; r++) {
            int f   = threadIdx.x + r * 256;
            int row = f >> 2;
            int c4  = (f & 3) << 2;
            float4 av = *(const float4*)(A + (size_t)(m0 + row) * K + k0 + c4);
            As[c4 + 0][row] = av.x; As[c4 + 1][row] = av.y;
            As[c4 + 2][row] = av.z; As[c4 + 3][row] = av.w;
            float4 wv = *(const float4*)(W + (size_t)(n0 + row) * K + k0 + c4);
            Ws[c4 + 0][row] = wv.x; Ws[c4 + 1][row] = wv.y;
            Ws[c4 + 2][row] = wv.z; Ws[c4 + 3][row] = wv.w;
        }
        __syncthreads();
        #pragma unroll
        for (int k = 0; k < 16; k++) {
            float a[8], b[8];
            *(float4*)(a)     = *(const float4*)(&As[k][ty * 8]);
            *(float4*)(a + 4) = *(const float4*)(&As[k][ty * 8 + 4]);
            *(float4*)(b)     = *(const float4*)(&Ws[k][tx * 8]);
            *(float4*)(b + 4) = *(const float4*)(&Ws[k][tx * 8 + 4]);
            #pragma unroll
            for (int i = 0; i < 8; i++)
                #pragma unroll
                for (int j = 0; j < 8; j++) acc[i][j] += a[i] * b[j];
        }
        __syncthreads();
    }
    #pragma unroll
    for (int i = 0; i < 8; i++) {
        size_t row = (size_t)(m0 + ty * 8 + i);
        float* crow = C + row * (size_t)N + n0 + tx * 8;
        const float* brow = bias + n0 + tx * 8;
        #pragma unroll
        for (int j = 0; j < 8; j += 4) {
            float4 o4 = make_float4(acc[i][j] + brow[j], acc[i][j + 1] + brow[j + 1],
                                    acc[i][j + 2] + brow[j + 2], acc[i][j + 3] + brow[j + 3]);
            *(float4*)(crow + j) = o4;
        }
    }
}

// ---------------- per-(token,head) norm + rope -> q/k/v [H][TOTAL][D] -------
__global__ void qkv_post_kernel(const float* __restrict__ qkvx, const float* __restrict__ qkvy,
                                const float* __restrict__ rcos, const float* __restrict__ rsin,
                                const float* __restrict__ qnx,  const float* __restrict__ knx,
                                const float* __restrict__ qny,  const float* __restrict__ kny,
                                const int* __restrict__ vidx,
                                float* __restrict__ qo, float* __restrict__ ko,
                                float* __restrict__ vo) {
    int i = blockIdx.x, h = blockIdx.y, d = threadIdx.x;
    int src = vidx[i];
    bool isx = src < NX;
    const float* base = isx ? (qkvx + (size_t)src * QKVC)
                            : (qkvy + (size_t)(src - NX) * QKVC);
    float qv = base[h * DD + d];
    float kv = base[DXC + h * DD + d];
    float vv = base[2 * DXC + h * DD + d];

    float qs = qv * qv, ks = kv * kv;
    #pragma unroll
    for (int o = 16; o > 0; o >>= 1) {
        qs += __shfl_xor_sync(0xffffffffu, qs, o);
        ks += __shfl_xor_sync(0xffffffffu, ks, o);
    }
    __shared__ float sq[4], sk[4];
    __shared__ float qsh[DD], ksh[DD];
    int wid = d >> 5;
    if ((d & 31) == 0) { sq[wid] = qs; sk[wid] = ks; }
    __syncthreads();
    float qss = sq[0] + sq[1] + sq[2] + sq[3];
    float kss = sk[0] + sk[1] + sk[2] + sk[3];
    float qn = qv * rsqrtf(qss / (float)DD + 1e-6f) * (isx ? qnx[d] : qny[d]);
    float kn = kv * rsqrtf(kss / (float)DD + 1e-6f) * (isx ? knx[d] : kny[d]);

    if (isx) {   // uniform branch per block
        qsh[d] = qn; ksh[d] = kn;
        __syncthreads();
        int j = d >> 1;
        float c  = rcos[((size_t)src * HH + h) * 64 + j];
        float sn = rsin[((size_t)src * HH + h) * 64 + j];
        if ((d & 1) == 0) {
            qn = qsh[d] * c - qsh[d + 1] * sn;
            kn = ksh[d] * c - ksh[d + 1] * sn;
        } else {
            qn = qsh[d - 1] * sn + qsh[d] * c;
            kn = ksh[d - 1] * sn + ksh[d] * c;
        }
    }
    size_t o = ((size_t)h * TOTALT + i) * DD + d;
    qo[o] = qn; ko[o] = kn; vo[o] = vv;
}

// ---------------- flash-style attention -------------------------------------
// grid (ceil(TOTAL/32), H), 128 threads = 4 warps (warp w owns d-chunk 32w..32w+31),
// lane l owns q-row i0+l. Online softmax, K-tile = 64, cross-warp score reduce in smem.
#define BQ  32
#define BKT 64

__global__ void attn_kernel(const float* __restrict__ qg, const float* __restrict__ kg,
                            const float* __restrict__ vg, const int* __restrict__ vidx,
                            float* __restrict__ full) {
    extern __shared__ float sm[];
    float* Ks = sm;                  // BKT*DD
    float* Vs = sm + BKT * DD;       // BKT*DD
    float* Sp = Vs + BKT * DD;       // [4][BQ][65]

    int h  = blockIdx.y;
    int i0 = blockIdx.x * BQ;
    int w  = threadIdx.x >> 5;
    int l  = threadIdx.x & 31;
    int qi = i0 + l;
    bool qvalid = qi < TOTALT;

    float qreg[32];
    {
        const float* qb = qg + ((size_t)h * TOTALT + (qvalid ? qi : 0)) * DD + w * 32;
        #pragma unroll
        for (int c = 0; c < 8; c++) {
            float4 t = *(const float4*)(qb + c * 4);
            qreg[c * 4 + 0] = t.x; qreg[c * 4 + 1] = t.y;
            qreg[c * 4 + 2] = t.z; qreg[c * 4 + 3] = t.w;
        }
    }
    float m = -1e30f, s = 0.f;
    float acc[32];
    #pragma unroll
    for (int c = 0; c < 32; c++) acc[c] = 0.f;
    const float scale = 0.08838834764831845f;  // 1/sqrt(128)
    const int ntiles = (TOTALT + BKT - 1) / BKT;

    for (int t = 0; t < ntiles; t++) {
        int kb = t * BKT;
        int nrows = TOTALT - kb; if (nrows > BKT) nrows = BKT;
        __syncthreads();
        {
            const float4* ksrc = (const float4*)(kg + ((size_t)h * TOTALT + kb) * DD);
            const float4* vsrc = (const float4*)(vg + ((size_t)h * TOTALT + kb) * DD);
            for (int f = threadIdx.x; f < BKT * DD / 4; f += 128) {
                int row = f >> 5;
                float4 kv = make_float4(0.f, 0.f, 0.f, 0.f), vv = kv;
                if (row < nrows) { kv = ksrc[f]; vv = vsrc[f]; }
                ((float4*)Ks)[f] = kv;
                ((float4*)Vs)[f] = vv;
            }
        }
        __syncthreads();
        // partial scores: this warp's 32-d chunk contribution for all 64 keys
        float* sp = Sp + ((size_t)w * BQ + l) * 65;
        for (int j = 0; j < BKT; j++) {
            const float4* kr = (const float4*)(Ks + j * DD + w * 32);
            float p = 0.f;
            #pragma unroll
            for (int c = 0; c < 8; c++) {
                float4 k4 = kr[c];
                p += qreg[c * 4 + 0] * k4.x + qreg[c * 4 + 1] * k4.y
                   + qreg[c * 4 + 2] * k4.z + qreg[c * 4 + 3] * k4.w;
            }
            sp[j] = p;
        }
        __syncthreads();
        // reduce the 4 d-chunk partials, scale, mask tail
        for (int e = threadIdx.x; e < BQ * BKT; e += 128) {
            int l2 = e >> 6;
            int j2 = e & 63;
            float ssum = Sp[(0 * BQ + l2) * 65 + j2] + Sp[(1 * BQ + l2) * 65 + j2]
                       + Sp[(2 * BQ + l2) * 65 + j2] + Sp[(3 * BQ + l2) * 65 + j2];
            Sp[(size_t)l2 * 65 + j2] = (kb + j2 < TOTALT) ? ssum * scale : -1e30f;
        }
        __syncthreads();
        // online softmax + PV (all 4 warps redundantly track m,s for their row)
        float* Srow = Sp + l * 65;
        float mt = m;
        for (int j = 0; j < BKT; j++) mt = fmaxf(mt, Srow[j]);
        float alpha = __expf(m - mt);
        m = mt;
        s *= alpha;
        #pragma unroll
        for (int c = 0; c < 32; c++) acc[c] *= alpha;
        for (int j = 0; j < BKT; j++) {
            float p = __expf(Srow[j] - mt);
            s += p;
            const float4* vr = (const float4*)(Vs + j * DD + w * 32);
            #pragma unroll
            for (int c = 0; c < 8; c++) {
                float4 v4 = vr[c];
                acc[c * 4 + 0] += p * v4.x; acc[c * 4 + 1] += p * v4.y;
                acc[c * 4 + 2] += p * v4.z; acc[c * 4 + 3] += p * v4.w;
            }
        }
    }
    if (qvalid) {
        float inv = 1.f / s;
        int dst = vidx[qi];
        float* orow = full + (size_t)dst * DXC + h * DD + w * 32;
        #pragma unroll
        for (int c = 0; c < 8; c++) {
            float4 o4 = make_float4(acc[c * 4 + 0] * inv, acc[c * 4 + 1] * inv,
                                    acc[c * 4 + 2] * inv, acc[c * 4 + 3] * inv);
            *(float4*)(orow + c * 4) = o4;
        }
    }
}

// ---------------- driver ----------------------------------------------------
extern "C" void kernel_launch(void* const* d_in, const int* in_sizes, int n_in,
                              void* d_out, int out_size) {
    const float* x       = (const float*)d_in[0];
    const float* y       = (const float*)d_in[1];
    const float* scale_x = (const float*)d_in[2];
    const float* scale_y = (const float*)d_in[3];
    const float* rcos    = (const float*)d_in[4];
    const float* rsin    = (const float*)d_in[5];
    const float* Wqkvx   = (const float*)d_in[6];
    const float* bqkvx   = (const float*)d_in[7];
    const float* Wqkvy   = (const float*)d_in[8];
    const float* bqkvy   = (const float*)d_in[9];
    const float* qnx     = (const float*)d_in[10];
    const float* knx     = (const float*)d_in[11];
    const float* qny     = (const float*)d_in[12];
    const float* kny     = (const float*)d_in[13];
    const float* Wpx     = (const float*)d_in[14];
    const float* bpx     = (const float*)d_in[15];
    const float* Wpy     = (const float*)d_in[16];
    const float* bpy     = (const float*)d_in[17];
    const int*   vidx    = (const int*)d_in[18];
    float* out = (float*)d_out;

    float *xm, *ym, *qkvx, *qkvy, *q, *k, *v, *full;
    cudaGetSymbolAddress((void**)&xm,   g_xm);
    cudaGetSymbolAddress((void**)&ym,   g_ym);
    cudaGetSymbolAddress((void**)&qkvx, g_qkvx);
    cudaGetSymbolAddress((void**)&qkvy, g_qkvy);
    cudaGetSymbolAddress((void**)&q,    g_q);
    cudaGetSymbolAddress((void**)&k,    g_k);
    cudaGetSymbolAddress((void**)&v,    g_v);
    cudaGetSymbolAddress((void**)&full, g_full);

    // 1. input rmsnorm + modulation
    rmsnorm_mod_kernel<<<NX, 256>>>(x, scale_x, xm, DXC);
    rmsnorm_mod_kernel<<<LY, 256>>>(y, scale_y, ym, DYC);
    zero_kernel<<<1024, 256>>>(full, (NX + LY) * DXC);

    // 2. qkv projections
    gemm_nt_bias<<<dim3(QKVC / 128, NX / 128), 256>>>(xm, Wqkvx, bqkvx, qkvx, NX, QKVC, DXC);
    gemm_nt_bias<<<dim3(QKVC / 128, LY / 128), 256>>>(ym, Wqkvy, bqkvy, qkvy, LY, QKVC, DYC);

    // 3. per-head norm + rope, gather valid tokens into [H][TOTAL][D]
    qkv_post_kernel<<<dim3(TOTALT, HH), 128>>>(qkvx, qkvy, rcos, rsin,
                                               qnx, knx, qny, kny, vidx, q, k, v);

    // 4. attention -> scatter into full
    const int ATTN_SMEM = (2 * BKT * DD + 4 * BQ * 65) * 4;  // 98816 B
    cudaFuncSetAttribute(attn_kernel, cudaFuncAttributeMaxDynamicSharedMemorySize, ATTN_SMEM);
    attn_kernel<<<dim3((TOTALT + BQ - 1) / BQ, HH), 128, ATTN_SMEM>>>(q, k, v, vidx, full);

    // 5. output projections
    gemm_nt_bias<<<dim3(DXC / 128, NX / 128), 256>>>(full, Wpx, bpx, out, NX, DXC, DXC);
    gemm_nt_bias<<<dim3(DYC / 128, LY / 128), 256>>>(full + (size_t)NX * DXC, Wpy, bpy,
                                                     out + (size_t)NX * DXC, LY, DYC, DXC);
}

// round 2
// speedup vs baseline: 1.5573x; 1.5573x over previous
#include <cuda_runtime.h>
#include <cstddef>

#define NX    2048
#define LY    256
#define HH    24
#define DD    128
#define DXC   3072
#define DYC   1536
#define QKVC  9216
#define TOTALT 2248

// ---------------- scratch (static device globals; no allocation) ------------
__device__ float g_xm  [(size_t)NX * DXC];
__device__ float g_ym  [(size_t)LY * DYC];
__device__ float g_qkvx[(size_t)NX * QKVC];
__device__ float g_qkvy[(size_t)LY * QKVC];
__device__ float g_q   [(size_t)HH * TOTALT * DD];
__device__ float g_k   [(size_t)HH * TOTALT * DD];
__device__ float g_v   [(size_t)HH * TOTALT * DD];
__device__ float g_full[(size_t)(NX + LY) * DXC];

// ---------------- rmsnorm * (1 + scale) ------------------------------------
__global__ void rmsnorm_mod_kernel(const float* __restrict__ x,
                                   const float* __restrict__ scale,
                                   float* __restrict__ out, int C) {
    int row = blockIdx.x;
    const float* xr = x + (size_t)row * C;
    float ss = 0.f;
    for (int c = threadIdx.x; c < C; c += blockDim.x) { float v = xr[c]; ss += v * v; }
    __shared__ float wsum[8];
    #pragma unroll
    for (int o = 16; o > 0; o >>= 1) ss += __shfl_xor_sync(0xffffffffu, ss, o);
    if ((threadIdx.x & 31) == 0) wsum[threadIdx.x >> 5] = ss;
    __syncthreads();
    float tot = 0.f;
    #pragma unroll
    for (int i = 0; i < 8; i++) tot += wsum[i];
    float r = rsqrtf(tot / (float)C + 1e-6f);
    float* orow = out + (size_t)row * C;
    for (int c = threadIdx.x; c < C; c += blockDim.x)
        orow[c] = xr[c] * r * (1.f + scale[c]);
}

// ---------------- zero fill --------------------------------------------------
__global__ void zero_kernel(float* __restrict__ p, int n) {
    for (int i = blockIdx.x * blockDim.x + threadIdx.x; i < n; i += gridDim.x * blockDim.x)
        p[i] = 0.f;
}

// ---------------- TF32 tensor-core NT GEMM ----------------------------------
// C[M,N] = A[M,K] * W[N,K]^T + bias.  BM=BN=128, BK=32, 256 thr = 8 warps (4x2).
// Warp tile 32x64: 2 m-tiles x 8 n-tiles of mma.m16n8k8.tf32.
// Smem row-major [128][36] (pad 36: frag loads and float4 stores conflict-free).
// Register-prefetch pipeline hides global latency.

__device__ __forceinline__ unsigned f2tf32(float f) {
    unsigned r;
    asm("cvt.rna.tf32.f32 %0, %1;" : "=r"(r) : "f"(f));
    return r;
}

__device__ __forceinline__ void mma_tf32(float* d, const unsigned* a, const unsigned* b) {
    asm volatile(
        "mma.sync.aligned.m16n8k8.row.col.f32.tf32.tf32.f32 "
        "{%0,%1,%2,%3}, {%4,%5,%6,%7}, {%8,%9}, {%0,%1,%2,%3};\n"
        : "+f"(d[0]), "+f"(d[1]), "+f"(d[2]), "+f"(d[3])
        : "r"(a[0]), "r"(a[1]), "r"(a[2]), "r"(a[3]), "r"(b[0]), "r"(b[1]));
}

#define SST 36   // smem row stride (floats)

__global__ void __launch_bounds__(256)
gemm_tf32_nt(const float* __restrict__ A, const float* __restrict__ W,
             const float* __restrict__ bias, float* __restrict__ C,
             int M, int N, int K) {
    __shared__ unsigned As[128 * SST];
    __shared__ unsigned Bs[128 * SST];
    const int tid  = threadIdx.x;
    const int lane = tid & 31;
    const int warp = tid >> 5;
    const int g    = lane >> 2;      // group id 0..7
    const int c    = lane & 3;       // thread-in-group 0..3
    const int wm   = warp >> 1;      // 0..3  (m)
    const int wn   = warp & 1;       // 0..1  (n)
    const int m0   = blockIdx.y * 128;
    const int n0   = blockIdx.x * 128;

    float acc[2][8][4];
    #pragma unroll
    for (int mt = 0; mt < 2; mt++)
        #pragma unroll
        for (int nt = 0; nt < 8; nt++)
            #pragma unroll
            for (int r = 0; r < 4; r++) acc[mt][nt][r] = 0.f;

    // loader mapping: idx = tid + r*256 -> row = idx>>3 (0..127), c4 = (idx&7)*4
    float4 pa[4], pb[4];
    const int niter = K / 32;

    // prologue: load + store tile 0
    #pragma unroll
    for (int r = 0; r < 4; r++) {
        int idx = tid + r * 256;
        int row = idx >> 3, c4 = (idx & 7) << 2;
        pa[r] = *(const float4*)(A + (size_t)(m0 + row) * K + c4);
        pb[r] = *(const float4*)(W + (size_t)(n0 + row) * K + c4);
    }
    #pragma unroll
    for (int r = 0; r < 4; r++) {
        int idx = tid + r * 256;
        int row = idx >> 3, c4 = (idx & 7) << 2;
        uint4 ua = make_uint4(f2tf32(pa[r].x), f2tf32(pa[r].y), f2tf32(pa[r].z), f2tf32(pa[r].w));
        uint4 ub = make_uint4(f2tf32(pb[r].x), f2tf32(pb[r].y), f2tf32(pb[r].z), f2tf32(pb[r].w));
        *(uint4*)(As + row * SST + c4) = ua;
        *(uint4*)(Bs + row * SST + c4) = ub;
    }
    __syncthreads();

    for (int it = 0; it < niter; it++) {
        // prefetch next K-slab into registers (overlaps with compute below)
        if (it + 1 < niter) {
            int k0 = (it + 1) * 32;
            #pragma unroll
            for (int r = 0; r < 4; r++) {
                int idx = tid + r * 256;
                int row = idx >> 3, c4 = (idx & 7) << 2;
                pa[r] = *(const float4*)(A + (size_t)(m0 + row) * K + k0 + c4);
                pb[r] = *(const float4*)(W + (size_t)(n0 + row) * K + k0 + c4);
            }
        }
        // compute on current smem tile
        #pragma unroll
        for (int ks = 0; ks < 32; ks += 8) {
            unsigned af[2][4], bf[8][2];
            #pragma unroll
            for (int mt = 0; mt < 2; mt++) {
                int mb = wm * 32 + mt * 16 + g;
                af[mt][0] = As[(mb)     * SST + ks + c];
                af[mt][1] = As[(mb + 8) * SST + ks + c];
                af[mt][2] = As[(mb)     * SST + ks + c + 4];
                af[mt][3] = As[(mb + 8) * SST + ks + c + 4];
            }
            #pragma unroll
            for (int nt = 0; nt < 8; nt++) {
                int nb = wn * 64 + nt * 8 + g;
                bf[nt][0] = Bs[nb * SST + ks + c];
                bf[nt][1] = Bs[nb * SST + ks + c + 4];
            }
            #pragma unroll
            for (int mt = 0; mt < 2; mt++)
                #pragma unroll
                for (int nt = 0; nt < 8; nt++)
                    mma_tf32(acc[mt][nt], af[mt], bf[nt]);
        }
        __syncthreads();
        if (it + 1 < niter) {
            #pragma unroll
            for (int r = 0; r < 4; r++) {
                int idx = tid + r * 256;
                int row = idx >> 3, c4 = (idx & 7) << 2;
                uint4 ua = make_uint4(f2tf32(pa[r].x), f2tf32(pa[r].y), f2tf32(pa[r].z), f2tf32(pa[r].w));
                uint4 ub = make_uint4(f2tf32(pb[r].x), f2tf32(pb[r].y), f2tf32(pb[r].z), f2tf32(pb[r].w));
                *(uint4*)(As + row * SST + c4) = ua;
                *(uint4*)(Bs + row * SST + c4) = ub;
            }
            __syncthreads();
        }
    }

    // epilogue: c0 (g,2c) c1 (g,2c+1) c2 (g+8,2c) c3 (g+8,2c+1)
    #pragma unroll
    for (int mt = 0; mt < 2; mt++) {
        int row = m0 + wm * 32 + mt * 16 + g;
        #pragma unroll
        for (int nt = 0; nt < 8; nt++) {
            int col = n0 + wn * 64 + nt * 8 + 2 * c;
            float b0 = bias[col], b1 = bias[col + 1];
            float2 v0 = make_float2(acc[mt][nt][0] + b0, acc[mt][nt][1] + b1);
            float2 v1 = make_float2(acc[mt][nt][2] + b0, acc[mt][nt][3] + b1);
            *(float2*)(C + (size_t)row * N + col)       = v0;
            *(float2*)(C + (size_t)(row + 8) * N + col) = v1;
        }
    }
}

// ---------------- per-(token,head) norm + rope -> q/k/v [H][TOTAL][D] -------
__global__ void qkv_post_kernel(const float* __restrict__ qkvx, const float* __restrict__ qkvy,
                                const float* __restrict__ rcos, const float* __restrict__ rsin,
                                const float* __restrict__ qnx,  const float* __restrict__ knx,
                                const float* __restrict__ qny,  const float* __restrict__ kny,
                                const int* __restrict__ vidx,
                                float* __restrict__ qo, float* __restrict__ ko,
                                float* __restrict__ vo) {
    int i = blockIdx.x, h = blockIdx.y, d = threadIdx.x;
    int src = vidx[i];
    bool isx = src < NX;
    const float* base = isx ? (qkvx + (size_t)src * QKVC)
                            : (qkvy + (size_t)(src - NX) * QKVC);
    float qv = base[h * DD + d];
    float kv = base[DXC + h * DD + d];
    float vv = base[2 * DXC + h * DD + d];

    float qs = qv * qv, ks = kv * kv;
    #pragma unroll
    for (int o = 16; o > 0; o >>= 1) {
        qs += __shfl_xor_sync(0xffffffffu, qs, o);
        ks += __shfl_xor_sync(0xffffffffu, ks, o);
    }
    __shared__ float sq[4], sk[4];
    __shared__ float qsh[DD], ksh[DD];
    int wid = d >> 5;
    if ((d & 31) == 0) { sq[wid] = qs; sk[wid] = ks; }
    __syncthreads();
    float qss = sq[0] + sq[1] + sq[2] + sq[3];
    float kss = sk[0] + sk[1] + sk[2] + sk[3];
    float qn = qv * rsqrtf(qss / (float)DD + 1e-6f) * (isx ? qnx[d] : qny[d]);
    float kn = kv * rsqrtf(kss / (float)DD + 1e-6f) * (isx ? knx[d] : kny[d]);

    if (isx) {   // uniform branch per block
        qsh[d] = qn; ksh[d] = kn;
        __syncthreads();
        int j = d >> 1;
        float cc = rcos[((size_t)src * HH + h) * 64 + j];
        float sn = rsin[((size_t)src * HH + h) * 64 + j];
        if ((d & 1) == 0) {
            qn = qsh[d] * cc - qsh[d + 1] * sn;
            kn = ksh[d] * cc - ksh[d + 1] * sn;
        } else {
            qn = qsh[d - 1] * sn + qsh[d] * cc;
            kn = ksh[d - 1] * sn + ksh[d] * cc;
        }
    }
    size_t o = ((size_t)h * TOTALT + i) * DD + d;
    qo[o] = qn; ko[o] = kn; vo[o] = vv;
}

// ---------------- flash-style attention -------------------------------------
#define BQ  32
#define BKT 64

__global__ void attn_kernel(const float* __restrict__ qg, const float* __restrict__ kg,
                            const float* __restrict__ vg, const int* __restrict__ vidx,
                            float* __restrict__ full) {
    extern __shared__ float sm[];
    float* Ks = sm;                  // BKT*DD
    float* Vs = sm + BKT * DD;       // BKT*DD
    float* Sp = Vs + BKT * DD;       // [4][BQ][65]

    int h  = blockIdx.y;
    int i0 = blockIdx.x * BQ;
    int w  = threadIdx.x >> 5;
    int l  = threadIdx.x & 31;
    int qi = i0 + l;
    bool qvalid = qi < TOTALT;

    float qreg[32];
    {
        const float* qb = qg + ((size_t)h * TOTALT + (qvalid ? qi : 0)) * DD + w * 32;
        #pragma unroll
        for (int c = 0; c < 8; c++) {
            float4 t = *(const float4*)(qb + c * 4);
            qreg[c * 4 + 0] = t.x; qreg[c * 4 + 1] = t.y;
            qreg[c * 4 + 2] = t.z; qreg[c * 4 + 3] = t.w;
        }
    }
    float m = -1e30f, s = 0.f;
    float acc[32];
    #pragma unroll
    for (int c = 0; c < 32; c++) acc[c] = 0.f;
    const float scale = 0.08838834764831845f;  // 1/sqrt(128)
    const int ntiles = (TOTALT + BKT - 1) / BKT;

    for (int t = 0; t < ntiles; t++) {
        int kb = t * BKT;
        int nrows = TOTALT - kb; if (nrows > BKT) nrows = BKT;
        __syncthreads();
        {
            const float4* ksrc = (const float4*)(kg + ((size_t)h * TOTALT + kb) * DD);
            const float4* vsrc = (const float4*)(vg + ((size_t)h * TOTALT + kb) * DD);
            for (int f = threadIdx.x; f < BKT * DD / 4; f += 128) {
                int row = f >> 5;
                float4 kv = make_float4(0.f, 0.f, 0.f, 0.f), vv = kv;
                if (row < nrows) { kv = ksrc[f]; vv = vsrc[f]; }
                ((float4*)Ks)[f] = kv;
                ((float4*)Vs)[f] = vv;
            }
        }
        __syncthreads();
        float* sp = Sp + ((size_t)w * BQ + l) * 65;
        for (int j = 0; j < BKT; j++) {
            const float4* kr = (const float4*)(Ks + j * DD + w * 32);
            float p = 0.f;
            #pragma unroll
            for (int c = 0; c < 8; c++) {
                float4 k4 = kr[c];
                p += qreg[c * 4 + 0] * k4.x + qreg[c * 4 + 1] * k4.y
                   + qreg[c * 4 + 2] * k4.z + qreg[c * 4 + 3] * k4.w;
            }
            sp[j] = p;
        }
        __syncthreads();
        for (int e = threadIdx.x; e < BQ * BKT; e += 128) {
            int l2 = e >> 6;
            int j2 = e & 63;
            float ssum = Sp[(0 * BQ + l2) * 65 + j2] + Sp[(1 * BQ + l2) * 65 + j2]
                       + Sp[(2 * BQ + l2) * 65 + j2] + Sp[(3 * BQ + l2) * 65 + j2];
            Sp[(size_t)l2 * 65 + j2] = (kb + j2 < TOTALT) ? ssum * scale : -1e30f;
        }
        __syncthreads();
        float* Srow = Sp + l * 65;
        float mt = m;
        for (int j = 0; j < BKT; j++) mt = fmaxf(mt, Srow[j]);
        float alpha = __expf(m - mt);
        m = mt;
        s *= alpha;
        #pragma unroll
        for (int c = 0; c < 32; c++) acc[c] *= alpha;
        for (int j = 0; j < BKT; j++) {
            float p = __expf(Srow[j] - mt);
            s += p;
            const float4* vr = (const float4*)(Vs + j * DD + w * 32);
            #pragma unroll
            for (int c = 0; c < 8; c++) {
                float4 v4 = vr[c];
                acc[c * 4 + 0] += p * v4.x; acc[c * 4 + 1] += p * v4.y;
                acc[c * 4 + 2] += p * v4.z; acc[c * 4 + 3] += p * v4.w;
            }
        }
    }
    if (qvalid) {
        float inv = 1.f / s;
        int dst = vidx[qi];
        float* orow = full + (size_t)dst * DXC + h * DD + w * 32;
        #pragma unroll
        for (int c = 0; c < 8; c++) {
            float4 o4 = make_float4(acc[c * 4 + 0] * inv, acc[c * 4 + 1] * inv,
                                    acc[c * 4 + 2] * inv, acc[c * 4 + 3] * inv);
            *(float4*)(orow + c * 4) = o4;
        }
    }
}

// ---------------- driver ----------------------------------------------------
extern "C" void kernel_launch(void* const* d_in, const int* in_sizes, int n_in,
                              void* d_out, int out_size) {
    const float* x       = (const float*)d_in[0];
    const float* y       = (const float*)d_in[1];
    const float* scale_x = (const float*)d_in[2];
    const float* scale_y = (const float*)d_in[3];
    const float* rcos    = (const float*)d_in[4];
    const float* rsin    = (const float*)d_in[5];
    const float* Wqkvx   = (const float*)d_in[6];
    const float* bqkvx   = (const float*)d_in[7];
    const float* Wqkvy   = (const float*)d_in[8];
    const float* bqkvy   = (const float*)d_in[9];
    const float* qnx     = (const float*)d_in[10];
    const float* knx     = (const float*)d_in[11];
    const float* qny     = (const float*)d_in[12];
    const float* kny     = (const float*)d_in[13];
    const float* Wpx     = (const float*)d_in[14];
    const float* bpx     = (const float*)d_in[15];
    const float* Wpy     = (const float*)d_in[16];
    const float* bpy     = (const float*)d_in[17];
    const int*   vidx    = (const int*)d_in[18];
    float* out = (float*)d_out;

    float *xm, *ym, *qkvx, *qkvy, *q, *k, *v, *full;
    cudaGetSymbolAddress((void**)&xm,   g_xm);
    cudaGetSymbolAddress((void**)&ym,   g_ym);
    cudaGetSymbolAddress((void**)&qkvx, g_qkvx);
    cudaGetSymbolAddress((void**)&qkvy, g_qkvy);
    cudaGetSymbolAddress((void**)&q,    g_q);
    cudaGetSymbolAddress((void**)&k,    g_k);
    cudaGetSymbolAddress((void**)&v,    g_v);
    cudaGetSymbolAddress((void**)&full, g_full);

    // 1. input rmsnorm + modulation
    rmsnorm_mod_kernel<<<NX, 256>>>(x, scale_x, xm, DXC);
    rmsnorm_mod_kernel<<<LY, 256>>>(y, scale_y, ym, DYC);
    zero_kernel<<<1024, 256>>>(full, (NX + LY) * DXC);

    // 2. qkv projections (TF32 tensor cores)
    gemm_tf32_nt<<<dim3(QKVC / 128, NX / 128), 256>>>(xm, Wqkvx, bqkvx, qkvx, NX, QKVC, DXC);
    gemm_tf32_nt<<<dim3(QKVC / 128, LY / 128), 256>>>(ym, Wqkvy, bqkvy, qkvy, LY, QKVC, DYC);

    // 3. per-head norm + rope, gather valid tokens into [H][TOTAL][D]
    qkv_post_kernel<<<dim3(TOTALT, HH), 128>>>(qkvx, qkvy, rcos, rsin,
                                               qnx, knx, qny, kny, vidx, q, k, v);

    // 4. attention -> scatter into full
    const int ATTN_SMEM = (2 * BKT * DD + 4 * BQ * 65) * 4;  // 98816 B
    cudaFuncSetAttribute(attn_kernel, cudaFuncAttributeMaxDynamicSharedMemorySize, ATTN_SMEM);
    attn_kernel<<<dim3((TOTALT + BQ - 1) / BQ, HH), 128, ATTN_SMEM>>>(q, k, v, vidx, full);

    // 5. output projections (TF32 tensor cores)
    gemm_tf32_nt<<<dim3(DXC / 128, NX / 128), 256>>>(full, Wpx, bpx, out, NX, DXC, DXC);
    gemm_tf32_nt<<<dim3(DYC / 128, LY / 128), 256>>>(full + (size_t)NX * DXC, Wpy, bpy,
                                                     out + (size_t)NX * DXC, LY, DYC, DXC);
}

// round 5
// speedup vs baseline: 2.9561x; 1.8983x over previous
#include <cuda_runtime.h>
#include <cstddef>

#define NX    2048
#define LY    256
#define HH    24
#define DD    128
#define DXC   3072
#define DYC   1536
#define QKVC  9216
#define TOTALT 2248

// ---------------- scratch (static device globals; no allocation) ------------
__device__ float g_xm  [(size_t)NX * DXC];
__device__ float g_ym  [(size_t)LY * DYC];
__device__ float g_qkvx[(size_t)NX * QKVC];
__device__ float g_qkvy[(size_t)LY * QKVC];
__device__ float g_q   [(size_t)HH * TOTALT * DD];
__device__ float g_k   [(size_t)HH * TOTALT * DD];
__device__ float g_v   [(size_t)HH * TOTALT * DD];
__device__ float g_full[(size_t)(NX + LY) * DXC];

// ---------------- common TF32 helpers ---------------------------------------
__device__ __forceinline__ unsigned f2tf32(float f) {
    unsigned r;
    asm("cvt.rna.tf32.f32 %0, %1;" : "=r"(r) : "f"(f));
    return r;
}

__device__ __forceinline__ void mma_tf32(float* d, const unsigned* a, const unsigned* b) {
    asm volatile(
        "mma.sync.aligned.m16n8k8.row.col.f32.tf32.tf32.f32 "
        "{%0,%1,%2,%3}, {%4,%5,%6,%7}, {%8,%9}, {%0,%1,%2,%3};\n"
        : "+f"(d[0]), "+f"(d[1]), "+f"(d[2]), "+f"(d[3])
        : "r"(a[0]), "r"(a[1]), "r"(a[2]), "r"(a[3]), "r"(b[0]), "r"(b[1]));
}

// ---------------- rmsnorm * (1 + scale) ------------------------------------
__global__ void rmsnorm_mod_kernel(const float* __restrict__ x,
                                   const float* __restrict__ scale,
                                   float* __restrict__ out, int C) {
    int row = blockIdx.x;
    const float* xr = x + (size_t)row * C;
    float ss = 0.f;
    for (int c = threadIdx.x; c < C; c += blockDim.x) { float v = xr[c]; ss += v * v; }
    __shared__ float wsum[8];
    #pragma unroll
    for (int o = 16; o > 0; o >>= 1) ss += __shfl_xor_sync(0xffffffffu, ss, o);
    if ((threadIdx.x & 31) == 0) wsum[threadIdx.x >> 5] = ss;
    __syncthreads();
    float tot = 0.f;
    #pragma unroll
    for (int i = 0; i < 8; i++) tot += wsum[i];
    float r = rsqrtf(tot / (float)C + 1e-6f);
    float* orow = out + (size_t)row * C;
    for (int c = threadIdx.x; c < C; c += blockDim.x)
        orow[c] = xr[c] * r * (1.f + scale[c]);
}

// ---------------- zero fill --------------------------------------------------
__global__ void zero_kernel(float* __restrict__ p, int n) {
    for (int i = blockIdx.x * blockDim.x + threadIdx.x; i < n; i += gridDim.x * blockDim.x)
        p[i] = 0.f;
}

// ---------------- TF32 tensor-core NT GEMM ----------------------------------
#define SST 36   // smem row stride (floats)

__global__ void __launch_bounds__(256)
gemm_tf32_nt(const float* __restrict__ A, const float* __restrict__ W,
             const float* __restrict__ bias, float* __restrict__ C,
             int M, int N, int K) {
    __shared__ unsigned As[128 * SST];
    __shared__ unsigned Bs[128 * SST];
    const int tid  = threadIdx.x;
    const int lane = tid & 31;
    const int warp = tid >> 5;
    const int g    = lane >> 2;
    const int c    = lane & 3;
    const int wm   = warp >> 1;
    const int wn   = warp & 1;
    const int m0   = blockIdx.y * 128;
    const int n0   = blockIdx.x * 128;

    float acc[2][8][4];
    #pragma unroll
    for (int mt = 0; mt < 2; mt++)
        #pragma unroll
        for (int nt = 0; nt < 8; nt++)
            #pragma unroll
            for (int r = 0; r < 4; r++) acc[mt][nt][r] = 0.f;

    float4 pa[4], pb[4];
    const int niter = K / 32;

    #pragma unroll
    for (int r = 0; r < 4; r++) {
        int idx = tid + r * 256;
        int row = idx >> 3, c4 = (idx & 7) << 2;
        pa[r] = *(const float4*)(A + (size_t)(m0 + row) * K + c4);
        pb[r] = *(const float4*)(W + (size_t)(n0 + row) * K + c4);
    }
    #pragma unroll
    for (int r = 0; r < 4; r++) {
        int idx = tid + r * 256;
        int row = idx >> 3, c4 = (idx & 7) << 2;
        uint4 ua = make_uint4(f2tf32(pa[r].x), f2tf32(pa[r].y), f2tf32(pa[r].z), f2tf32(pa[r].w));
        uint4 ub = make_uint4(f2tf32(pb[r].x), f2tf32(pb[r].y), f2tf32(pb[r].z), f2tf32(pb[r].w));
        *(uint4*)(As + row * SST + c4) = ua;
        *(uint4*)(Bs + row * SST + c4) = ub;
    }
    __syncthreads();

    for (int it = 0; it < niter; it++) {
        if (it + 1 < niter) {
            int k0 = (it + 1) * 32;
            #pragma unroll
            for (int r = 0; r < 4; r++) {
                int idx = tid + r * 256;
                int row = idx >> 3, c4 = (idx & 7) << 2;
                pa[r] = *(const float4*)(A + (size_t)(m0 + row) * K + k0 + c4);
                pb[r] = *(const float4*)(W + (size_t)(n0 + row) * K + k0 + c4);
            }
        }
        #pragma unroll
        for (int ks = 0; ks < 32; ks += 8) {
            unsigned af[2][4], bf[8][2];
            #pragma unroll
            for (int mt = 0; mt < 2; mt++) {
                int mb = wm * 32 + mt * 16 + g;
                af[mt][0] = As[(mb)     * SST + ks + c];
                af[mt][1] = As[(mb + 8) * SST + ks + c];
                af[mt][2] = As[(mb)     * SST + ks + c + 4];
                af[mt][3] = As[(mb + 8) * SST + ks + c + 4];
            }
            #pragma unroll
            for (int nt = 0; nt < 8; nt++) {
                int nb = wn * 64 + nt * 8 + g;
                bf[nt][0] = Bs[nb * SST + ks + c];
                bf[nt][1] = Bs[nb * SST + ks + c + 4];
            }
            #pragma unroll
            for (int mt = 0; mt < 2; mt++)
                #pragma unroll
                for (int nt = 0; nt < 8; nt++)
                    mma_tf32(acc[mt][nt], af[mt], bf[nt]);
        }
        __syncthreads();
        if (it + 1 < niter) {
            #pragma unroll
            for (int r = 0; r < 4; r++) {
                int idx = tid + r * 256;
                int row = idx >> 3, c4 = (idx & 7) << 2;
                uint4 ua = make_uint4(f2tf32(pa[r].x), f2tf32(pa[r].y), f2tf32(pa[r].z), f2tf32(pa[r].w));
                uint4 ub = make_uint4(f2tf32(pb[r].x), f2tf32(pb[r].y), f2tf32(pb[r].z), f2tf32(pb[r].w));
                *(uint4*)(As + row * SST + c4) = ua;
                *(uint4*)(Bs + row * SST + c4) = ub;
            }
            __syncthreads();
        }
    }

    #pragma unroll
    for (int mt = 0; mt < 2; mt++) {
        int row = m0 + wm * 32 + mt * 16 + g;
        #pragma unroll
        for (int nt = 0; nt < 8; nt++) {
            int col = n0 + wn * 64 + nt * 8 + 2 * c;
            float b0 = bias[col], b1 = bias[col + 1];
            float2 v0 = make_float2(acc[mt][nt][0] + b0, acc[mt][nt][1] + b1);
            float2 v1 = make_float2(acc[mt][nt][2] + b0, acc[mt][nt][3] + b1);
            *(float2*)(C + (size_t)row * N + col)       = v0;
            *(float2*)(C + (size_t)(row + 8) * N + col) = v1;
        }
    }
}

// ---------------- per-(token,head) norm + rope -> q/k/v [H][TOTAL][D] -------
__global__ void qkv_post_kernel(const float* __restrict__ qkvx, const float* __restrict__ qkvy,
                                const float* __restrict__ rcos, const float* __restrict__ rsin,
                                const float* __restrict__ qnx,  const float* __restrict__ knx,
                                const float* __restrict__ qny,  const float* __restrict__ kny,
                                const int* __restrict__ vidx,
                                float* __restrict__ qo, float* __restrict__ ko,
                                float* __restrict__ vo) {
    int i = blockIdx.x, h = blockIdx.y, d = threadIdx.x;
    int src = vidx[i];
    bool isx = src < NX;
    const float* base = isx ? (qkvx + (size_t)src * QKVC)
                            : (qkvy + (size_t)(src - NX) * QKVC);
    float qv = base[h * DD + d];
    float kv = base[DXC + h * DD + d];
    float vv = base[2 * DXC + h * DD + d];

    float qs = qv * qv, ks = kv * kv;
    #pragma unroll
    for (int o = 16; o > 0; o >>= 1) {
        qs += __shfl_xor_sync(0xffffffffu, qs, o);
        ks += __shfl_xor_sync(0xffffffffu, ks, o);
    }
    __shared__ float sq[4], sk[4];
    __shared__ float qsh[DD], ksh[DD];
    int wid = d >> 5;
    if ((d & 31) == 0) { sq[wid] = qs; sk[wid] = ks; }
    __syncthreads();
    float qss = sq[0] + sq[1] + sq[2] + sq[3];
    float kss = sk[0] + sk[1] + sk[2] + sk[3];
    float qn = qv * rsqrtf(qss / (float)DD + 1e-6f) * (isx ? qnx[d] : qny[d]);
    float kn = kv * rsqrtf(kss / (float)DD + 1e-6f) * (isx ? knx[d] : kny[d]);

    if (isx) {
        qsh[d] = qn; ksh[d] = kn;
        __syncthreads();
        int j = d >> 1;
        float cc = rcos[((size_t)src * HH + h) * 64 + j];
        float sn = rsin[((size_t)src * HH + h) * 64 + j];
        if ((d & 1) == 0) {
            qn = qsh[d] * cc - qsh[d + 1] * sn;
            kn = ksh[d] * cc - ksh[d + 1] * sn;
        } else {
            qn = qsh[d - 1] * sn + qsh[d] * cc;
            kn = ksh[d - 1] * sn + ksh[d] * cc;
        }
    }
    size_t o = ((size_t)h * TOTALT + i) * DD + d;
    qo[o] = qn; ko[o] = kn; vo[o] = vv;
}

// ---------------- TF32 tensor-core flash attention ---------------------------
// 256 thr = 8 warps; BQ=128 (16 q-rows per warp), BK=64, D=128.
#define AQS 132
#define AVS 68
#define ABQ 128
#define ABK 64

__global__ void __launch_bounds__(256)
attn_mma_kernel(const float* __restrict__ qg, const float* __restrict__ kg,
                const float* __restrict__ vg, const int* __restrict__ vidx,
                float* __restrict__ full) {
    extern __shared__ unsigned asm_[];
    unsigned* Qs = asm_;                    // 128*132
    unsigned* Ks = Qs + ABQ * AQS;          // 64*132
    unsigned* Vt = Ks + ABK * AQS;          // 128*68
    unsigned* Ps = Vt + DD * AVS;           // 128*68

    const int h    = blockIdx.y;
    const int i0   = blockIdx.x * ABQ;
    const int tid  = threadIdx.x;
    const int lane = tid & 31;
    const int warp = tid >> 5;
    const int g    = lane >> 2;
    const int c    = lane & 3;
    const int q4   = lane >> 2;
    const int wr16 = warp * 16;
    const float scale = 0.08838834764831845f;

    const float* qh = qg + (size_t)h * TOTALT * DD;
    const float* kh = kg + (size_t)h * TOTALT * DD;
    const float* vh = vg + (size_t)h * TOTALT * DD;

    // ---- load Q tile (scaled, tf32) ----
    #pragma unroll
    for (int it = 0; it < 16; it++) {
        int f = tid + it * 256;
        int row = f >> 5, c4 = (f & 31) << 2;
        int qi = i0 + row; if (qi >= TOTALT) qi = TOTALT - 1;
        float4 t = *(const float4*)(qh + (size_t)qi * DD + c4);
        Qs[row * AQS + c4 + 0] = f2tf32(t.x * scale);
        Qs[row * AQS + c4 + 1] = f2tf32(t.y * scale);
        Qs[row * AQS + c4 + 2] = f2tf32(t.z * scale);
        Qs[row * AQS + c4 + 3] = f2tf32(t.w * scale);
    }

    float o[16][4];
    #pragma unroll
    for (int nt = 0; nt < 16; nt++)
        #pragma unroll
        for (int r = 0; r < 4; r++) o[nt][r] = 0.f;
    float m0 = -1e30f, m1 = -1e30f, l0 = 0.f, l1 = 0.f;

    const int ntiles = (TOTALT + ABK - 1) / ABK;
    for (int t = 0; t < ntiles; t++) {
        const int kb = t * ABK;
        __syncthreads();
        // ---- load K tile (tf32) ----
        #pragma unroll
        for (int it = 0; it < 8; it++) {
            int f = tid + it * 256;
            int row = f >> 5, c4 = (f & 31) << 2;
            int kidx = kb + row; if (kidx >= TOTALT) kidx = TOTALT - 1;
            float4 tv = *(const float4*)(kh + (size_t)kidx * DD + c4);
            Ks[row * AQS + c4 + 0] = f2tf32(tv.x);
            Ks[row * AQS + c4 + 1] = f2tf32(tv.y);
            Ks[row * AQS + c4 + 2] = f2tf32(tv.z);
            Ks[row * AQS + c4 + 3] = f2tf32(tv.w);
        }
        // ---- load V tile transposed: Vt[d][j] = V[kb+j][d] ----
        #pragma unroll
        for (int it = 0; it < 8; it++) {
            int ci = it * 8 + warp;
            int rg = ci & 15;
            int cc = ci >> 4;
            int jb = rg * 4;
            int d0 = cc * 32 + q4 * 4;
            int jrow = kb + jb + c; if (jrow >= TOTALT) jrow = TOTALT - 1;
            float4 tv = *(const float4*)(vh + (size_t)jrow * DD + d0);
            const float* tp = &tv.x;
            #pragma unroll
            for (int ii = 0; ii < 4; ii++) {
                int i = (ii + q4) & 3;
                Vt[(d0 + i) * AVS + jb + c] = f2tf32(tp[i]);
            }
        }
        __syncthreads();

        // ---- S = Q K^T  (warp: 16 x 64) ----
        float s[8][4];
        #pragma unroll
        for (int nt = 0; nt < 8; nt++)
            #pragma unroll
            for (int r = 0; r < 4; r++) s[nt][r] = 0.f;
        #pragma unroll
        for (int ks = 0; ks < 16; ks++) {
            unsigned af[4], bf[8][2];
            int mb = wr16 + g;
            af[0] = Qs[(mb)     * AQS + ks * 8 + c];
            af[1] = Qs[(mb + 8) * AQS + ks * 8 + c];
            af[2] = Qs[(mb)     * AQS + ks * 8 + c + 4];
            af[3] = Qs[(mb + 8) * AQS + ks * 8 + c + 4];
            #pragma unroll
            for (int nt = 0; nt < 8; nt++) {
                bf[nt][0] = Ks[(nt * 8 + g) * AQS + ks * 8 + c];
                bf[nt][1] = Ks[(nt * 8 + g) * AQS + ks * 8 + c + 4];
            }
            #pragma unroll
            for (int nt = 0; nt < 8; nt++)
                mma_tf32(s[nt], af, bf[nt]);
        }

        // ---- mask tail ----
        if (kb + ABK > TOTALT) {
            #pragma unroll
            for (int nt = 0; nt < 8; nt++) {
                int j0 = kb + nt * 8 + 2 * c;
                if (j0     >= TOTALT) { s[nt][0] = -1e30f; s[nt][2] = -1e30f; }
                if (j0 + 1 >= TOTALT) { s[nt][1] = -1e30f; s[nt][3] = -1e30f; }
            }
        }

        // ---- online softmax (rows g and g+8) ----
        float tmax0 = -1e30f, tmax1 = -1e30f;
        #pragma unroll
        for (int nt = 0; nt < 8; nt++) {
            tmax0 = fmaxf(tmax0, fmaxf(s[nt][0], s[nt][1]));
            tmax1 = fmaxf(tmax1, fmaxf(s[nt][2], s[nt][3]));
        }
        tmax0 = fmaxf(tmax0, __shfl_xor_sync(0xffffffffu, tmax0, 1));
        tmax0 = fmaxf(tmax0, __shfl_xor_sync(0xffffffffu, tmax0, 2));
        tmax1 = fmaxf(tmax1, __shfl_xor_sync(0xffffffffu, tmax1, 1));
        tmax1 = fmaxf(tmax1, __shfl_xor_sync(0xffffffffu, tmax1, 2));
        float mn0 = fmaxf(m0, tmax0), mn1 = fmaxf(m1, tmax1);
        float a0 = __expf(m0 - mn0), a1 = __expf(m1 - mn1);
        m0 = mn0; m1 = mn1;

        float ps0 = 0.f, ps1 = 0.f;
        #pragma unroll
        for (int nt = 0; nt < 8; nt++) {
            s[nt][0] = __expf(s[nt][0] - mn0);
            s[nt][1] = __expf(s[nt][1] - mn0);
            s[nt][2] = __expf(s[nt][2] - mn1);
            s[nt][3] = __expf(s[nt][3] - mn1);
            ps0 += s[nt][0] + s[nt][1];
            ps1 += s[nt][2] + s[nt][3];
        }
        ps0 += __shfl_xor_sync(0xffffffffu, ps0, 1);
        ps0 += __shfl_xor_sync(0xffffffffu, ps0, 2);
        ps1 += __shfl_xor_sync(0xffffffffu, ps1, 1);
        ps1 += __shfl_xor_sync(0xffffffffu, ps1, 2);
        l0 = l0 * a0 + ps0;
        l1 = l1 * a1 + ps1;
        #pragma unroll
        for (int nt = 0; nt < 16; nt++) {
            o[nt][0] *= a0; o[nt][1] *= a0;
            o[nt][2] *= a1; o[nt][3] *= a1;
        }

        // ---- store P (tf32) to per-warp smem region ----
        #pragma unroll
        for (int nt = 0; nt < 8; nt++) {
            *(uint2*)(Ps + (wr16 + g)     * AVS + nt * 8 + 2 * c) =
                make_uint2(f2tf32(s[nt][0]), f2tf32(s[nt][1]));
            *(uint2*)(Ps + (wr16 + g + 8) * AVS + nt * 8 + 2 * c) =
                make_uint2(f2tf32(s[nt][2]), f2tf32(s[nt][3]));
        }
        __syncwarp();

        // ---- O += P V  (warp: 16 x 128, k = 64) ----
        #pragma unroll
        for (int ks2 = 0; ks2 < 8; ks2++) {
            unsigned af[4];
            af[0] = Ps[(wr16 + g)     * AVS + ks2 * 8 + c];
            af[1] = Ps[(wr16 + g + 8) * AVS + ks2 * 8 + c];
            af[2] = Ps[(wr16 + g)     * AVS + ks2 * 8 + c + 4];
            af[3] = Ps[(wr16 + g + 8) * AVS + ks2 * 8 + c + 4];
            #pragma unroll
            for (int nt2 = 0; nt2 < 16; nt2++) {
                unsigned bf[2];
                bf[0] = Vt[(nt2 * 8 + g) * AVS + ks2 * 8 + c];
                bf[1] = Vt[(nt2 * 8 + g) * AVS + ks2 * 8 + c + 4];
                mma_tf32(o[nt2], af, bf);
            }
        }
    }

    // ---- epilogue ----
    float inv0 = 1.f / l0, inv1 = 1.f / l1;
    int r0 = i0 + wr16 + g, r1 = r0 + 8;
    if (r0 < TOTALT) {
        int dst = vidx[r0];
        float* orow = full + (size_t)dst * DXC + h * DD;
        #pragma unroll
        for (int nt2 = 0; nt2 < 16; nt2++)
            *(float2*)(orow + nt2 * 8 + 2 * c) =
                make_float2(o[nt2][0] * inv0, o[nt2][1] * inv0);
    }
    if (r1 < TOTALT) {
        int dst = vidx[r1];
        float* orow = full + (size_t)dst * DXC + h * DD;
        #pragma unroll
        for (int nt2 = 0; nt2 < 16; nt2++)
            *(float2*)(orow + nt2 * 8 + 2 * c) =
                make_float2(o[nt2][2] * inv1, o[nt2][3] * inv1);
    }
}

// ---------------- driver ----------------------------------------------------
extern "C" void kernel_launch(void* const* d_in, const int* in_sizes, int n_in,
                              void* d_out, int out_size) {
    const float* x       = (const float*)d_in[0];
    const float* y       = (const float*)d_in[1];
    const float* scale_x = (const float*)d_in[2];
    const float* scale_y = (const float*)d_in[3];
    const float* rcos    = (const float*)d_in[4];
    const float* rsin    = (const float*)d_in[5];
    const float* Wqkvx   = (const float*)d_in[6];
    const float* bqkvx   = (const float*)d_in[7];
    const float* Wqkvy   = (const float*)d_in[8];
    const float* bqkvy   = (const float*)d_in[9];
    const float* qnx     = (const float*)d_in[10];
    const float* knx     = (const float*)d_in[11];
    const float* qny     = (const float*)d_in[12];
    const float* kny     = (const float*)d_in[13];
    const float* Wpx     = (const float*)d_in[14];
    const float* bpx     = (const float*)d_in[15];
    const float* Wpy     = (const float*)d_in[16];
    const float* bpy     = (const float*)d_in[17];
    const int*   vidx    = (const int*)d_in[18];
    float* out = (float*)d_out;

    float *xm, *ym, *qkvx, *qkvy, *q, *k, *v, *full;
    cudaGetSymbolAddress((void**)&xm,   g_xm);
    cudaGetSymbolAddress((void**)&ym,   g_ym);
    cudaGetSymbolAddress((void**)&qkvx, g_qkvx);
    cudaGetSymbolAddress((void**)&qkvy, g_qkvy);
    cudaGetSymbolAddress((void**)&q,    g_q);
    cudaGetSymbolAddress((void**)&k,    g_k);
    cudaGetSymbolAddress((void**)&v,    g_v);
    cudaGetSymbolAddress((void**)&full, g_full);

    // 1. input rmsnorm + modulation
    rmsnorm_mod_kernel<<<NX, 256>>>(x, scale_x, xm, DXC);
    rmsnorm_mod_kernel<<<LY, 256>>>(y, scale_y, ym, DYC);
    zero_kernel<<<1024, 256>>>(full, (NX + LY) * DXC);

    // 2. qkv projections (TF32 tensor cores)
    gemm_tf32_nt<<<dim3(QKVC / 128, NX / 128), 256>>>(xm, Wqkvx, bqkvx, qkvx, NX, QKVC, DXC);
    gemm_tf32_nt<<<dim3(QKVC / 128, LY / 128), 256>>>(ym, Wqkvy, bqkvy, qkvy, LY, QKVC, DYC);

    // 3. per-head norm + rope, gather valid tokens into [H][TOTAL][D]
    qkv_post_kernel<<<dim3(TOTALT, HH), 128>>>(qkvx, qkvy, rcos, rsin,
                                               qnx, knx, qny, kny, vidx, q, k, v);

    // 4. attention (TF32 tensor cores) -> scatter into full
    const int ATTN_SMEM = (ABQ * AQS + ABK * AQS + DD * AVS + ABQ * AVS) * 4;  // 171008 B
    cudaFuncSetAttribute(attn_mma_kernel, cudaFuncAttributeMaxDynamicSharedMemorySize, ATTN_SMEM);
    attn_mma_kernel<<<dim3((TOTALT + ABQ - 1) / ABQ, HH), 256, ATTN_SMEM>>>(q, k, v, vidx, full);

    // 5. output projections (TF32 tensor cores)
    gemm_tf32_nt<<<dim3(DXC / 128, NX / 128), 256>>>(full, Wpx, bpx, out, NX, DXC, DXC);
    gemm_tf32_nt<<<dim3(DYC / 128, LY / 128), 256>>>(full + (size_t)NX * DXC, Wpy, bpy,
                                                     out + (size_t)NX * DXC, LY, DYC, DXC);
}

// round 6
// speedup vs baseline: 2.9608x; 1.0016x over previous
#include <cuda_runtime.h>
#include <cstddef>

#define NX    2048
#define LY    256
#define HH    24
#define DD    128
#define DXC   3072
#define DYC   1536
#define QKVC  9216
#define TOTALT 2248

// ---------------- scratch (static device globals; no allocation) ------------
__device__ float g_xm  [(size_t)NX * DXC];
__device__ float g_ym  [(size_t)LY * DYC];
__device__ float g_qkvx[(size_t)NX * QKVC];
__device__ float g_qkvy[(size_t)LY * QKVC];
__device__ float g_q   [(size_t)HH * TOTALT * DD];
__device__ float g_k   [(size_t)HH * TOTALT * DD];
__device__ float g_v   [(size_t)HH * TOTALT * DD];
__device__ float g_full[(size_t)(NX + LY) * DXC];

// ---------------- common TF32 / async helpers --------------------------------
__device__ __forceinline__ unsigned f2tf32(float f) {
    unsigned r;
    asm("cvt.rna.tf32.f32 %0, %1;" : "=r"(r) : "f"(f));
    return r;
}

__device__ __forceinline__ void mma_tf32(float* d, const unsigned* a, const unsigned* b) {
    asm volatile(
        "mma.sync.aligned.m16n8k8.row.col.f32.tf32.tf32.f32 "
        "{%0,%1,%2,%3}, {%4,%5,%6,%7}, {%8,%9}, {%0,%1,%2,%3};\n"
        : "+f"(d[0]), "+f"(d[1]), "+f"(d[2]), "+f"(d[3])
        : "r"(a[0]), "r"(a[1]), "r"(a[2]), "r"(a[3]), "r"(b[0]), "r"(b[1]));
}

__device__ __forceinline__ void cpasync16(float* dst, const float* src) {
    unsigned d = (unsigned)__cvta_generic_to_shared(dst);
    asm volatile("cp.async.cg.shared.global [%0], [%1], 16;" :: "r"(d), "l"(src));
}
__device__ __forceinline__ void cp_commit() {
    asm volatile("cp.async.commit_group;");
}
template <int N_>
__device__ __forceinline__ void cp_wait() {
    asm volatile("cp.async.wait_group %0;" :: "n"(N_));
}

// ---------------- rmsnorm * (1 + scale) ------------------------------------
__global__ void rmsnorm_mod_kernel(const float* __restrict__ x,
                                   const float* __restrict__ scale,
                                   float* __restrict__ out, int C) {
    int row = blockIdx.x;
    const float* xr = x + (size_t)row * C;
    float ss = 0.f;
    for (int c = threadIdx.x; c < C; c += blockDim.x) { float v = xr[c]; ss += v * v; }
    __shared__ float wsum[8];
    #pragma unroll
    for (int o = 16; o > 0; o >>= 1) ss += __shfl_xor_sync(0xffffffffu, ss, o);
    if ((threadIdx.x & 31) == 0) wsum[threadIdx.x >> 5] = ss;
    __syncthreads();
    float tot = 0.f;
    #pragma unroll
    for (int i = 0; i < 8; i++) tot += wsum[i];
    float r = rsqrtf(tot / (float)C + 1e-6f);
    float* orow = out + (size_t)row * C;
    for (int c = threadIdx.x; c < C; c += blockDim.x)
        orow[c] = xr[c] * r * (1.f + scale[c]);
}

// ---------------- zero fill --------------------------------------------------
__global__ void zero_kernel(float* __restrict__ p, int n) {
    for (int i = blockIdx.x * blockDim.x + threadIdx.x; i < n; i += gridDim.x * blockDim.x)
        p[i] = 0.f;
}

// ---------------- TF32 NT GEMM, 128x128 block (small-M GEMMs) ---------------
#define SST 36

__global__ void __launch_bounds__(256)
gemm_tf32_nt(const float* __restrict__ A, const float* __restrict__ W,
             const float* __restrict__ bias, float* __restrict__ C,
             int M, int N, int K) {
    __shared__ unsigned As[128 * SST];
    __shared__ unsigned Bs[128 * SST];
    const int tid  = threadIdx.x;
    const int lane = tid & 31;
    const int warp = tid >> 5;
    const int g    = lane >> 2;
    const int c    = lane & 3;
    const int wm   = warp >> 1;
    const int wn   = warp & 1;
    const int m0   = blockIdx.y * 128;
    const int n0   = blockIdx.x * 128;

    float acc[2][8][4];
    #pragma unroll
    for (int mt = 0; mt < 2; mt++)
        #pragma unroll
        for (int nt = 0; nt < 8; nt++)
            #pragma unroll
            for (int r = 0; r < 4; r++) acc[mt][nt][r] = 0.f;

    float4 pa[4], pb[4];
    const int niter = K / 32;

    #pragma unroll
    for (int r = 0; r < 4; r++) {
        int idx = tid + r * 256;
        int row = idx >> 3, c4 = (idx & 7) << 2;
        pa[r] = *(const float4*)(A + (size_t)(m0 + row) * K + c4);
        pb[r] = *(const float4*)(W + (size_t)(n0 + row) * K + c4);
    }
    #pragma unroll
    for (int r = 0; r < 4; r++) {
        int idx = tid + r * 256;
        int row = idx >> 3, c4 = (idx & 7) << 2;
        uint4 ua = make_uint4(f2tf32(pa[r].x), f2tf32(pa[r].y), f2tf32(pa[r].z), f2tf32(pa[r].w));
        uint4 ub = make_uint4(f2tf32(pb[r].x), f2tf32(pb[r].y), f2tf32(pb[r].z), f2tf32(pb[r].w));
        *(uint4*)(As + row * SST + c4) = ua;
        *(uint4*)(Bs + row * SST + c4) = ub;
    }
    __syncthreads();

    for (int it = 0; it < niter; it++) {
        if (it + 1 < niter) {
            int k0 = (it + 1) * 32;
            #pragma unroll
            for (int r = 0; r < 4; r++) {
                int idx = tid + r * 256;
                int row = idx >> 3, c4 = (idx & 7) << 2;
                pa[r] = *(const float4*)(A + (size_t)(m0 + row) * K + k0 + c4);
                pb[r] = *(const float4*)(W + (size_t)(n0 + row) * K + k0 + c4);
            }
        }
        #pragma unroll
        for (int ks = 0; ks < 32; ks += 8) {
            unsigned af[2][4], bf[8][2];
            #pragma unroll
            for (int mt = 0; mt < 2; mt++) {
                int mb = wm * 32 + mt * 16 + g;
                af[mt][0] = As[(mb)     * SST + ks + c];
                af[mt][1] = As[(mb + 8) * SST + ks + c];
                af[mt][2] = As[(mb)     * SST + ks + c + 4];
                af[mt][3] = As[(mb + 8) * SST + ks + c + 4];
            }
            #pragma unroll
            for (int nt = 0; nt < 8; nt++) {
                int nb = wn * 64 + nt * 8 + g;
                bf[nt][0] = Bs[nb * SST + ks + c];
                bf[nt][1] = Bs[nb * SST + ks + c + 4];
            }
            #pragma unroll
            for (int mt = 0; mt < 2; mt++)
                #pragma unroll
                for (int nt = 0; nt < 8; nt++)
                    mma_tf32(acc[mt][nt], af[mt], bf[nt]);
        }
        __syncthreads();
        if (it + 1 < niter) {
            #pragma unroll
            for (int r = 0; r < 4; r++) {
                int idx = tid + r * 256;
                int row = idx >> 3, c4 = (idx & 7) << 2;
                uint4 ua = make_uint4(f2tf32(pa[r].x), f2tf32(pa[r].y), f2tf32(pa[r].z), f2tf32(pa[r].w));
                uint4 ub = make_uint4(f2tf32(pb[r].x), f2tf32(pb[r].y), f2tf32(pb[r].z), f2tf32(pb[r].w));
                *(uint4*)(As + row * SST + c4) = ua;
                *(uint4*)(Bs + row * SST + c4) = ub;
            }
            __syncthreads();
        }
    }

    #pragma unroll
    for (int mt = 0; mt < 2; mt++) {
        int row = m0 + wm * 32 + mt * 16 + g;
        #pragma unroll
        for (int nt = 0; nt < 8; nt++) {
            int col = n0 + wn * 64 + nt * 8 + 2 * c;
            float b0 = bias[col], b1 = bias[col + 1];
            float2 v0 = make_float2(acc[mt][nt][0] + b0, acc[mt][nt][1] + b1);
            float2 v1 = make_float2(acc[mt][nt][2] + b0, acc[mt][nt][3] + b1);
            *(float2*)(C + (size_t)row * N + col)       = v0;
            *(float2*)(C + (size_t)(row + 8) * N + col) = v1;
        }
    }
}

// ---------------- TF32 NT GEMM, 128x256 block, 64x64 warp tiles --------------
// 8 warps (2 wm x 4 wn), BK=16, cp.async 2-stage double buffer of raw fp32,
// tf32 conversion at fragment load. Cuts smem crossbar bytes/MMA: ceiling 55%.
#define SST2 20          // smem row stride (floats), 80B rows: 16B-aligned, conflict-free frags

__global__ void __launch_bounds__(256)
gemm_tf32_big(const float* __restrict__ A, const float* __restrict__ W,
              const float* __restrict__ bias, float* __restrict__ C,
              int M, int N, int K) {
    extern __shared__ float smg[];
    float* As = smg;                         // [2][128*SST2]
    float* Bs = smg + 2 * 128 * SST2;        // [2][256*SST2]

    const int tid  = threadIdx.x;
    const int lane = tid & 31;
    const int warp = tid >> 5;
    const int g    = lane >> 2;
    const int c    = lane & 3;
    const int wm   = warp >> 2;              // 0..1
    const int wn   = warp & 3;               // 0..3
    const int m0   = blockIdx.y * 128;
    const int n0   = blockIdx.x * 256;

    float acc[4][8][4];
    #pragma unroll
    for (int mt = 0; mt < 4; mt++)
        #pragma unroll
        for (int nt = 0; nt < 8; nt++)
            #pragma unroll
            for (int r = 0; r < 4; r++) acc[mt][nt][r] = 0.f;

    const int niter = K / 16;

    // stage loader: A 128x16 (512 f4, 2/thread), B 256x16 (1024 f4, 4/thread)
    auto load_stage = [&](int s, int k0) {
        float* as = As + s * 128 * SST2;
        float* bs = Bs + s * 256 * SST2;
        #pragma unroll
        for (int r = 0; r < 2; r++) {
            int idx = tid + r * 256;
            int row = idx >> 2, c4 = (idx & 3) << 2;
            cpasync16(as + row * SST2 + c4, A + (size_t)(m0 + row) * K + k0 + c4);
        }
        #pragma unroll
        for (int r = 0; r < 4; r++) {
            int idx = tid + r * 256;
            int row = idx >> 2, c4 = (idx & 3) << 2;
            cpasync16(bs + row * SST2 + c4, W + (size_t)(n0 + row) * K + k0 + c4);
        }
    };

    load_stage(0, 0);
    cp_commit();

    for (int it = 0; it < niter; it++) {
        if (it + 1 < niter) {
            load_stage((it + 1) & 1, (it + 1) * 16);
            cp_commit();
            cp_wait<1>();
        } else {
            cp_wait<0>();
        }
        __syncthreads();

        const float* as = As + (it & 1) * 128 * SST2;
        const float* bs = Bs + (it & 1) * 256 * SST2;
        #pragma unroll
        for (int ks = 0; ks < 2; ks++) {
            unsigned af[4][4], bf[8][2];
            #pragma unroll
            for (int mt = 0; mt < 4; mt++) {
                int mb = wm * 64 + mt * 16 + g;
                af[mt][0] = f2tf32(as[(mb)     * SST2 + ks * 8 + c]);
                af[mt][1] = f2tf32(as[(mb + 8) * SST2 + ks * 8 + c]);
                af[mt][2] = f2tf32(as[(mb)     * SST2 + ks * 8 + c + 4]);
                af[mt][3] = f2tf32(as[(mb + 8) * SST2 + ks * 8 + c + 4]);
            }
            #pragma unroll
            for (int nt = 0; nt < 8; nt++) {
                int nb = wn * 64 + nt * 8 + g;
                bf[nt][0] = f2tf32(bs[nb * SST2 + ks * 8 + c]);
                bf[nt][1] = f2tf32(bs[nb * SST2 + ks * 8 + c + 4]);
            }
            #pragma unroll
            for (int mt = 0; mt < 4; mt++)
                #pragma unroll
                for (int nt = 0; nt < 8; nt++)
                    mma_tf32(acc[mt][nt], af[mt], bf[nt]);
        }
        __syncthreads();
    }

    #pragma unroll
    for (int mt = 0; mt < 4; mt++) {
        int row = m0 + wm * 64 + mt * 16 + g;
        #pragma unroll
        for (int nt = 0; nt < 8; nt++) {
            int col = n0 + wn * 64 + nt * 8 + 2 * c;
            float b0 = bias[col], b1 = bias[col + 1];
            float2 v0 = make_float2(acc[mt][nt][0] + b0, acc[mt][nt][1] + b1);
            float2 v1 = make_float2(acc[mt][nt][2] + b0, acc[mt][nt][3] + b1);
            *(float2*)(C + (size_t)row * N + col)       = v0;
            *(float2*)(C + (size_t)(row + 8) * N + col) = v1;
        }
    }
}
#define GEMM_BIG_SMEM ((2 * 128 * SST2 + 2 * 256 * SST2) * 4)   // 61440 B

// ---------------- per-(token,head) norm + rope -> q/k/v [H][TOTAL][D] -------
__global__ void qkv_post_kernel(const float* __restrict__ qkvx, const float* __restrict__ qkvy,
                                const float* __restrict__ rcos, const float* __restrict__ rsin,
                                const float* __restrict__ qnx,  const float* __restrict__ knx,
                                const float* __restrict__ qny,  const float* __restrict__ kny,
                                const int* __restrict__ vidx,
                                float* __restrict__ qo, float* __restrict__ ko,
                                float* __restrict__ vo) {
    int i = blockIdx.x, h = blockIdx.y, d = threadIdx.x;
    int src = vidx[i];
    bool isx = src < NX;
    const float* base = isx ? (qkvx + (size_t)src * QKVC)
                            : (qkvy + (size_t)(src - NX) * QKVC);
    float qv = base[h * DD + d];
    float kv = base[DXC + h * DD + d];
    float vv = base[2 * DXC + h * DD + d];

    float qs = qv * qv, ks = kv * kv;
    #pragma unroll
    for (int o = 16; o > 0; o >>= 1) {
        qs += __shfl_xor_sync(0xffffffffu, qs, o);
        ks += __shfl_xor_sync(0xffffffffu, ks, o);
    }
    __shared__ float sq[4], sk[4];
    __shared__ float qsh[DD], ksh[DD];
    int wid = d >> 5;
    if ((d & 31) == 0) { sq[wid] = qs; sk[wid] = ks; }
    __syncthreads();
    float qss = sq[0] + sq[1] + sq[2] + sq[3];
    float kss = sk[0] + sk[1] + sk[2] + sk[3];
    float qn = qv * rsqrtf(qss / (float)DD + 1e-6f) * (isx ? qnx[d] : qny[d]);
    float kn = kv * rsqrtf(kss / (float)DD + 1e-6f) * (isx ? knx[d] : kny[d]);

    if (isx) {
        qsh[d] = qn; ksh[d] = kn;
        __syncthreads();
        int j = d >> 1;
        float cc = rcos[((size_t)src * HH + h) * 64 + j];
        float sn = rsin[((size_t)src * HH + h) * 64 + j];
        if ((d & 1) == 0) {
            qn = qsh[d] * cc - qsh[d + 1] * sn;
            kn = ksh[d] * cc - ksh[d + 1] * sn;
        } else {
            qn = qsh[d - 1] * sn + qsh[d] * cc;
            kn = ksh[d - 1] * sn + ksh[d] * cc;
        }
    }
    size_t o = ((size_t)h * TOTALT + i) * DD + d;
    qo[o] = qn; ko[o] = kn; vo[o] = vv;
}

// ---------------- TF32 tensor-core flash attention ---------------------------
#define AQS 132
#define AVS 68
#define ABQ 128
#define ABK 64

__global__ void __launch_bounds__(256)
attn_mma_kernel(const float* __restrict__ qg, const float* __restrict__ kg,
                const float* __restrict__ vg, const int* __restrict__ vidx,
                float* __restrict__ full) {
    extern __shared__ unsigned asm_[];
    unsigned* Qs = asm_;                    // 128*132
    unsigned* Ks = Qs + ABQ * AQS;          // 64*132
    unsigned* Vt = Ks + ABK * AQS;          // 128*68
    unsigned* Ps = Vt + DD * AVS;           // 128*68

    const int h    = blockIdx.y;
    const int i0   = blockIdx.x * ABQ;
    const int tid  = threadIdx.x;
    const int lane = tid & 31;
    const int warp = tid >> 5;
    const int g    = lane >> 2;
    const int c    = lane & 3;
    const int q4   = lane >> 2;
    const int wr16 = warp * 16;
    const float scale = 0.08838834764831845f;

    const float* qh = qg + (size_t)h * TOTALT * DD;
    const float* kh = kg + (size_t)h * TOTALT * DD;
    const float* vh = vg + (size_t)h * TOTALT * DD;

    #pragma unroll
    for (int it = 0; it < 16; it++) {
        int f = tid + it * 256;
        int row = f >> 5, c4 = (f & 31) << 2;
        int qi = i0 + row; if (qi >= TOTALT) qi = TOTALT - 1;
        float4 t = *(const float4*)(qh + (size_t)qi * DD + c4);
        Qs[row * AQS + c4 + 0] = f2tf32(t.x * scale);
        Qs[row * AQS + c4 + 1] = f2tf32(t.y * scale);
        Qs[row * AQS + c4 + 2] = f2tf32(t.z * scale);
        Qs[row * AQS + c4 + 3] = f2tf32(t.w * scale);
    }

    float o[16][4];
    #pragma unroll
    for (int nt = 0; nt < 16; nt++)
        #pragma unroll
        for (int r = 0; r < 4; r++) o[nt][r] = 0.f;
    float m0 = -1e30f, m1 = -1e30f, l0 = 0.f, l1 = 0.f;

    const int ntiles = (TOTALT + ABK - 1) / ABK;
    for (int t = 0; t < ntiles; t++) {
        const int kb = t * ABK;
        __syncthreads();
        #pragma unroll
        for (int it = 0; it < 8; it++) {
            int f = tid + it * 256;
            int row = f >> 5, c4 = (f & 31) << 2;
            int kidx = kb + row; if (kidx >= TOTALT) kidx = TOTALT - 1;
            float4 tv = *(const float4*)(kh + (size_t)kidx * DD + c4);
            Ks[row * AQS + c4 + 0] = f2tf32(tv.x);
            Ks[row * AQS + c4 + 1] = f2tf32(tv.y);
            Ks[row * AQS + c4 + 2] = f2tf32(tv.z);
            Ks[row * AQS + c4 + 3] = f2tf32(tv.w);
        }
        #pragma unroll
        for (int it = 0; it < 8; it++) {
            int ci = it * 8 + warp;
            int rg = ci & 15;
            int cc = ci >> 4;
            int jb = rg * 4;
            int d0 = cc * 32 + q4 * 4;
            int jrow = kb + jb + c; if (jrow >= TOTALT) jrow = TOTALT - 1;
            float4 tv = *(const float4*)(vh + (size_t)jrow * DD + d0);
            const float* tp = &tv.x;
            #pragma unroll
            for (int ii = 0; ii < 4; ii++) {
                int i = (ii + q4) & 3;
                Vt[(d0 + i) * AVS + jb + c] = f2tf32(tp[i]);
            }
        }
        __syncthreads();

        float s[8][4];
        #pragma unroll
        for (int nt = 0; nt < 8; nt++)
            #pragma unroll
            for (int r = 0; r < 4; r++) s[nt][r] = 0.f;
        #pragma unroll
        for (int ks = 0; ks < 16; ks++) {
            unsigned af[4], bf[8][2];
            int mb = wr16 + g;
            af[0] = Qs[(mb)     * AQS + ks * 8 + c];
            af[1] = Qs[(mb + 8) * AQS + ks * 8 + c];
            af[2] = Qs[(mb)     * AQS + ks * 8 + c + 4];
            af[3] = Qs[(mb + 8) * AQS + ks * 8 + c + 4];
            #pragma unroll
            for (int nt = 0; nt < 8; nt++) {
                bf[nt][0] = Ks[(nt * 8 + g) * AQS + ks * 8 + c];
                bf[nt][1] = Ks[(nt * 8 + g) * AQS + ks * 8 + c + 4];
            }
            #pragma unroll
            for (int nt = 0; nt < 8; nt++)
                mma_tf32(s[nt], af, bf[nt]);
        }

        if (kb + ABK > TOTALT) {
            #pragma unroll
            for (int nt = 0; nt < 8; nt++) {
                int j0 = kb + nt * 8 + 2 * c;
                if (j0     >= TOTALT) { s[nt][0] = -1e30f; s[nt][2] = -1e30f; }
                if (j0 + 1 >= TOTALT) { s[nt][1] = -1e30f; s[nt][3] = -1e30f; }
            }
        }

        float tmax0 = -1e30f, tmax1 = -1e30f;
        #pragma unroll
        for (int nt = 0; nt < 8; nt++) {
            tmax0 = fmaxf(tmax0, fmaxf(s[nt][0], s[nt][1]));
            tmax1 = fmaxf(tmax1, fmaxf(s[nt][2], s[nt][3]));
        }
        tmax0 = fmaxf(tmax0, __shfl_xor_sync(0xffffffffu, tmax0, 1));
        tmax0 = fmaxf(tmax0, __shfl_xor_sync(0xffffffffu, tmax0, 2));
        tmax1 = fmaxf(tmax1, __shfl_xor_sync(0xffffffffu, tmax1, 1));
        tmax1 = fmaxf(tmax1, __shfl_xor_sync(0xffffffffu, tmax1, 2));
        float mn0 = fmaxf(m0, tmax0), mn1 = fmaxf(m1, tmax1);
        float a0 = __expf(m0 - mn0), a1 = __expf(m1 - mn1);
        m0 = mn0; m1 = mn1;

        float ps0 = 0.f, ps1 = 0.f;
        #pragma unroll
        for (int nt = 0; nt < 8; nt++) {
            s[nt][0] = __expf(s[nt][0] - mn0);
            s[nt][1] = __expf(s[nt][1] - mn0);
            s[nt][2] = __expf(s[nt][2] - mn1);
            s[nt][3] = __expf(s[nt][3] - mn1);
            ps0 += s[nt][0] + s[nt][1];
            ps1 += s[nt][2] + s[nt][3];
        }
        ps0 += __shfl_xor_sync(0xffffffffu, ps0, 1);
        ps0 += __shfl_xor_sync(0xffffffffu, ps0, 2);
        ps1 += __shfl_xor_sync(0xffffffffu, ps1, 1);
        ps1 += __shfl_xor_sync(0xffffffffu, ps1, 2);
        l0 = l0 * a0 + ps0;
        l1 = l1 * a1 + ps1;
        #pragma unroll
        for (int nt = 0; nt < 16; nt++) {
            o[nt][0] *= a0; o[nt][1] *= a0;
            o[nt][2] *= a1; o[nt][3] *= a1;
        }

        #pragma unroll
        for (int nt = 0; nt < 8; nt++) {
            *(uint2*)(Ps + (wr16 + g)     * AVS + nt * 8 + 2 * c) =
                make_uint2(f2tf32(s[nt][0]), f2tf32(s[nt][1]));
            *(uint2*)(Ps + (wr16 + g + 8) * AVS + nt * 8 + 2 * c) =
                make_uint2(f2tf32(s[nt][2]), f2tf32(s[nt][3]));
        }
        __syncwarp();

        #pragma unroll
        for (int ks2 = 0; ks2 < 8; ks2++) {
            unsigned af[4];
            af[0] = Ps[(wr16 + g)     * AVS + ks2 * 8 + c];
            af[1] = Ps[(wr16 + g + 8) * AVS + ks2 * 8 + c];
            af[2] = Ps[(wr16 + g)     * AVS + ks2 * 8 + c + 4];
            af[3] = Ps[(wr16 + g + 8) * AVS + ks2 * 8 + c + 4];
            #pragma unroll
            for (int nt2 = 0; nt2 < 16; nt2++) {
                unsigned bf[2];
                bf[0] = Vt[(nt2 * 8 + g) * AVS + ks2 * 8 + c];
                bf[1] = Vt[(nt2 * 8 + g) * AVS + ks2 * 8 + c + 4];
                mma_tf32(o[nt2], af, bf);
            }
        }
    }

    float inv0 = 1.f / l0, inv1 = 1.f / l1;
    int r0 = i0 + wr16 + g, r1 = r0 + 8;
    if (r0 < TOTALT) {
        int dst = vidx[r0];
        float* orow = full + (size_t)dst * DXC + h * DD;
        #pragma unroll
        for (int nt2 = 0; nt2 < 16; nt2++)
            *(float2*)(orow + nt2 * 8 + 2 * c) =
                make_float2(o[nt2][0] * inv0, o[nt2][1] * inv0);
    }
    if (r1 < TOTALT) {
        int dst = vidx[r1];
        float* orow = full + (size_t)dst * DXC + h * DD;
        #pragma unroll
        for (int nt2 = 0; nt2 < 16; nt2++)
            *(float2*)(orow + nt2 * 8 + 2 * c) =
                make_float2(o[nt2][2] * inv1, o[nt2][3] * inv1);
    }
}

// ---------------- driver ----------------------------------------------------
extern "C" void kernel_launch(void* const* d_in, const int* in_sizes, int n_in,
                              void* d_out, int out_size) {
    const float* x       = (const float*)d_in[0];
    const float* y       = (const float*)d_in[1];
    const float* scale_x = (const float*)d_in[2];
    const float* scale_y = (const float*)d_in[3];
    const float* rcos    = (const float*)d_in[4];
    const float* rsin    = (const float*)d_in[5];
    const float* Wqkvx   = (const float*)d_in[6];
    const float* bqkvx   = (const float*)d_in[7];
    const float* Wqkvy   = (const float*)d_in[8];
    const float* bqkvy   = (const float*)d_in[9];
    const float* qnx     = (const float*)d_in[10];
    const float* knx     = (const float*)d_in[11];
    const float* qny     = (const float*)d_in[12];
    const float* kny     = (const float*)d_in[13];
    const float* Wpx     = (const float*)d_in[14];
    const float* bpx     = (const float*)d_in[15];
    const float* Wpy     = (const float*)d_in[16];
    const float* bpy     = (const float*)d_in[17];
    const int*   vidx    = (const int*)d_in[18];
    float* out = (float*)d_out;

    float *xm, *ym, *qkvx, *qkvy, *q, *k, *v, *full;
    cudaGetSymbolAddress((void**)&xm,   g_xm);
    cudaGetSymbolAddress((void**)&ym,   g_ym);
    cudaGetSymbolAddress((void**)&qkvx, g_qkvx);
    cudaGetSymbolAddress((void**)&qkvy, g_qkvy);
    cudaGetSymbolAddress((void**)&q,    g_q);
    cudaGetSymbolAddress((void**)&k,    g_k);
    cudaGetSymbolAddress((void**)&v,    g_v);
    cudaGetSymbolAddress((void**)&full, g_full);

    // 1. input rmsnorm + modulation
    rmsnorm_mod_kernel<<<NX, 256>>>(x, scale_x, xm, DXC);
    rmsnorm_mod_kernel<<<LY, 256>>>(y, scale_y, ym, DYC);
    zero_kernel<<<1024, 256>>>(full, (NX + LY) * DXC);

    // 2. qkv projections
    cudaFuncSetAttribute(gemm_tf32_big, cudaFuncAttributeMaxDynamicSharedMemorySize, GEMM_BIG_SMEM);
    gemm_tf32_big<<<dim3(QKVC / 256, NX / 128), 256, GEMM_BIG_SMEM>>>(xm, Wqkvx, bqkvx, qkvx, NX, QKVC, DXC);
    gemm_tf32_nt<<<dim3(QKVC / 128, LY / 128), 256>>>(ym, Wqkvy, bqkvy, qkvy, LY, QKVC, DYC);

    // 3. per-head norm + rope, gather valid tokens into [H][TOTAL][D]
    qkv_post_kernel<<<dim3(TOTALT, HH), 128>>>(qkvx, qkvy, rcos, rsin,
                                               qnx, knx, qny, kny, vidx, q, k, v);

    // 4. attention (TF32 tensor cores) -> scatter into full
    const int ATTN_SMEM = (ABQ * AQS + ABK * AQS + DD * AVS + ABQ * AVS) * 4;  // 171008 B
    cudaFuncSetAttribute(attn_mma_kernel, cudaFuncAttributeMaxDynamicSharedMemorySize, ATTN_SMEM);
    attn_mma_kernel<<<dim3((TOTALT + ABQ - 1) / ABQ, HH), 256, ATTN_SMEM>>>(q, k, v, vidx, full);

    // 5. output projections
    gemm_tf32_big<<<dim3(DXC / 256, NX / 128), 256, GEMM_BIG_SMEM>>>(full, Wpx, bpx, out, NX, DXC, DXC);
    gemm_tf32_nt<<<dim3(DYC / 128, LY / 128), 256>>>(full + (size_t)NX * DXC, Wpy, bpy,
                                                     out + (size_t)NX * DXC, LY, DYC, DXC);
}

// round 8
// speedup vs baseline: 3.0104x; 1.0167x over previous
#include <cuda_runtime.h>
#include <cstddef>
#include <cstdint>

#define NX    2048
#define LY    256
#define HH    24
#define DD    128
#define DXC   3072
#define DYC   1536
#define QKVC  9216
#define TOTALT 2248

// ---------------- scratch (static device globals; no allocation) ------------
__device__ float g_xm  [(size_t)NX * DXC];
__device__ float g_ym  [(size_t)LY * DYC];
__device__ float g_qkvx[(size_t)NX * QKVC];
__device__ float g_qkvy[(size_t)LY * QKVC];
__device__ float g_q   [(size_t)HH * TOTALT * DD];
__device__ float g_k   [(size_t)HH * TOTALT * DD];
__device__ float g_v   [(size_t)HH * TOTALT * DD];
__device__ float g_full[(size_t)(NX + LY) * DXC];
__device__ float g_wqx [(size_t)3 * DXC * DXC];   // tf32-rounded W_qkv_x
__device__ float g_wpx [(size_t)DXC * DXC];       // tf32-rounded W_proj_x

// ---------------- helpers ----------------------------------------------------
__device__ __forceinline__ unsigned f2tf32(float f) {
    unsigned r;
    asm("cvt.rna.tf32.f32 %0, %1;" : "=r"(r) : "f"(f));
    return r;
}

__device__ __forceinline__ void mma_tf32(float* d, const unsigned* a, const unsigned* b) {
    asm volatile(
        "mma.sync.aligned.m16n8k8.row.col.f32.tf32.tf32.f32 "
        "{%0,%1,%2,%3}, {%4,%5,%6,%7}, {%8,%9}, {%0,%1,%2,%3};\n"
        : "+f"(d[0]), "+f"(d[1]), "+f"(d[2]), "+f"(d[3])
        : "r"(a[0]), "r"(a[1]), "r"(a[2]), "r"(a[3]), "r"(b[0]), "r"(b[1]));
}

__device__ __forceinline__ void cpasync16(float* dst, const float* src) {
    unsigned d = (unsigned)__cvta_generic_to_shared(dst);
    asm volatile("cp.async.cg.shared.global [%0], [%1], 16;" :: "r"(d), "l"(src));
}
__device__ __forceinline__ void cp_commit() {
    asm volatile("cp.async.commit_group;");
}
template <int N_>
__device__ __forceinline__ void cp_wait() {
    asm volatile("cp.async.wait_group %0;" :: "n"(N_));
}

// ---------------- tf32 rounding pass (weights) -------------------------------
__global__ void round_tf32_kernel(const float* __restrict__ in, float* __restrict__ out, int n) {
    for (int i = blockIdx.x * blockDim.x + threadIdx.x; i < n; i += gridDim.x * blockDim.x)
        out[i] = __uint_as_float(f2tf32(in[i]));
}

// ---------------- rmsnorm * (1 + scale), tf32-rounded output -----------------
__global__ void rmsnorm_mod_kernel(const float* __restrict__ x,
                                   const float* __restrict__ scale,
                                   float* __restrict__ out, int C) {
    int row = blockIdx.x;
    const float* xr = x + (size_t)row * C;
    float ss = 0.f;
    for (int c = threadIdx.x; c < C; c += blockDim.x) { float v = xr[c]; ss += v * v; }
    __shared__ float wsum[8];
    #pragma unroll
    for (int o = 16; o > 0; o >>= 1) ss += __shfl_xor_sync(0xffffffffu, ss, o);
    if ((threadIdx.x & 31) == 0) wsum[threadIdx.x >> 5] = ss;
    __syncthreads();
    float tot = 0.f;
    #pragma unroll
    for (int i = 0; i < 8; i++) tot += wsum[i];
    float r = rsqrtf(tot / (float)C + 1e-6f);
    float* orow = out + (size_t)row * C;
    for (int c = threadIdx.x; c < C; c += blockDim.x)
        orow[c] = __uint_as_float(f2tf32(xr[c] * r * (1.f + scale[c])));
}

// ---------------- zero fill --------------------------------------------------
__global__ void zero_kernel(float* __restrict__ p, int n) {
    for (int i = blockIdx.x * blockDim.x + threadIdx.x; i < n; i += gridDim.x * blockDim.x)
        p[i] = 0.f;
}

// ---------------- TF32 NT GEMM, 128x128 (small y-GEMMs, self-converting) -----
#define SST 36

__global__ void __launch_bounds__(256)
gemm_tf32_nt(const float* __restrict__ A, const float* __restrict__ W,
             const float* __restrict__ bias, float* __restrict__ C,
             int M, int N, int K) {
    __shared__ unsigned As[128 * SST];
    __shared__ unsigned Bs[128 * SST];
    const int tid  = threadIdx.x;
    const int lane = tid & 31;
    const int warp = tid >> 5;
    const int g    = lane >> 2;
    const int c    = lane & 3;
    const int wm   = warp >> 1;
    const int wn   = warp & 1;
    const int m0   = blockIdx.y * 128;
    const int n0   = blockIdx.x * 128;

    float acc[2][8][4];
    #pragma unroll
    for (int mt = 0; mt < 2; mt++)
        #pragma unroll
        for (int nt = 0; nt < 8; nt++)
            #pragma unroll
            for (int r = 0; r < 4; r++) acc[mt][nt][r] = 0.f;

    float4 pa[4], pb[4];
    const int niter = K / 32;

    #pragma unroll
    for (int r = 0; r < 4; r++) {
        int idx = tid + r * 256;
        int row = idx >> 3, c4 = (idx & 7) << 2;
        pa[r] = *(const float4*)(A + (size_t)(m0 + row) * K + c4);
        pb[r] = *(const float4*)(W + (size_t)(n0 + row) * K + c4);
    }
    #pragma unroll
    for (int r = 0; r < 4; r++) {
        int idx = tid + r * 256;
        int row = idx >> 3, c4 = (idx & 7) << 2;
        uint4 ua = make_uint4(f2tf32(pa[r].x), f2tf32(pa[r].y), f2tf32(pa[r].z), f2tf32(pa[r].w));
        uint4 ub = make_uint4(f2tf32(pb[r].x), f2tf32(pb[r].y), f2tf32(pb[r].z), f2tf32(pb[r].w));
        *(uint4*)(As + row * SST + c4) = ua;
        *(uint4*)(Bs + row * SST + c4) = ub;
    }
    __syncthreads();

    for (int it = 0; it < niter; it++) {
        if (it + 1 < niter) {
            int k0 = (it + 1) * 32;
            #pragma unroll
            for (int r = 0; r < 4; r++) {
                int idx = tid + r * 256;
                int row = idx >> 3, c4 = (idx & 7) << 2;
                pa[r] = *(const float4*)(A + (size_t)(m0 + row) * K + k0 + c4);
                pb[r] = *(const float4*)(W + (size_t)(n0 + row) * K + k0 + c4);
            }
        }
        #pragma unroll
        for (int ks = 0; ks < 32; ks += 8) {
            unsigned af[2][4], bf[8][2];
            #pragma unroll
            for (int mt = 0; mt < 2; mt++) {
                int mb = wm * 32 + mt * 16 + g;
                af[mt][0] = As[(mb)     * SST + ks + c];
                af[mt][1] = As[(mb + 8) * SST + ks + c];
                af[mt][2] = As[(mb)     * SST + ks + c + 4];
                af[mt][3] = As[(mb + 8) * SST + ks + c + 4];
            }
            #pragma unroll
            for (int nt = 0; nt < 8; nt++) {
                int nb = wn * 64 + nt * 8 + g;
                bf[nt][0] = Bs[nb * SST + ks + c];
                bf[nt][1] = Bs[nb * SST + ks + c + 4];
            }
            #pragma unroll
            for (int mt = 0; mt < 2; mt++)
                #pragma unroll
                for (int nt = 0; nt < 8; nt++)
                    mma_tf32(acc[mt][nt], af[mt], bf[nt]);
        }
        __syncthreads();
        if (it + 1 < niter) {
            #pragma unroll
            for (int r = 0; r < 4; r++) {
                int idx = tid + r * 256;
                int row = idx >> 3, c4 = (idx & 7) << 2;
                uint4 ua = make_uint4(f2tf32(pa[r].x), f2tf32(pa[r].y), f2tf32(pa[r].z), f2tf32(pa[r].w));
                uint4 ub = make_uint4(f2tf32(pb[r].x), f2tf32(pb[r].y), f2tf32(pb[r].z), f2tf32(pb[r].w));
                *(uint4*)(As + row * SST + c4) = ua;
                *(uint4*)(Bs + row * SST + c4) = ub;
            }
            __syncthreads();
        }
    }

    #pragma unroll
    for (int mt = 0; mt < 2; mt++) {
        int row = m0 + wm * 32 + mt * 16 + g;
        #pragma unroll
        for (int nt = 0; nt < 8; nt++) {
            int col = n0 + wn * 64 + nt * 8 + 2 * c;
            float b0 = bias[col], b1 = bias[col + 1];
            float2 v0 = make_float2(acc[mt][nt][0] + b0, acc[mt][nt][1] + b1);
            float2 v1 = make_float2(acc[mt][nt][2] + b0, acc[mt][nt][3] + b1);
            *(float2*)(C + (size_t)row * N + col)       = v0;
            *(float2*)(C + (size_t)(row + 8) * N + col) = v1;
        }
    }
}

// ---------------- TF32 NT GEMM, 128x256, 4-stage cp.async pipeline -----------
// Inputs MUST be pre-rounded to tf32. Pure cp.async + LDS + MMA hot loop.
// 8 warps (2x4), 64x64 warp tiles, BK=16, stages rotate through 4 smem slots.
#define MS_STGA (128 * 20)
#define MS_STGB (256 * 20)
#define MS_STG  (MS_STGA + MS_STGB)
#define MS_SMEM (4 * MS_STG * 4)     // 122880 B

__global__ void __launch_bounds__(256)
gemm_tf32_ms(const float* __restrict__ A, const float* __restrict__ W,
             const float* __restrict__ bias, float* __restrict__ C,
             int M, int N, int K) {
    extern __shared__ float sm[];
    const int tid  = threadIdx.x;
    const int lane = tid & 31;
    const int warp = tid >> 5;
    const int g    = lane >> 2;
    const int c    = lane & 3;
    const int wm   = warp >> 2;              // 0..1
    const int wn   = warp & 3;               // 0..3
    const int m0   = blockIdx.y * 128;
    const int n0   = blockIdx.x * 256;

    float acc[4][8][4];
    #pragma unroll
    for (int mt = 0; mt < 4; mt++)
        #pragma unroll
        for (int nt = 0; nt < 8; nt++)
            #pragma unroll
            for (int r = 0; r < 4; r++) acc[mt][nt][r] = 0.f;

    const int niter = K / 16;

    auto load_stage = [&](int s, int k0) {
        float* as = sm + s * MS_STG;
        float* bs = as + MS_STGA;
        #pragma unroll
        for (int r = 0; r < 2; r++) {
            int idx = tid + r * 256;
            int row = idx >> 2, c4 = (idx & 3) << 2;
            cpasync16(as + row * 20 + c4, A + (size_t)(m0 + row) * K + k0 + c4);
        }
        #pragma unroll
        for (int r = 0; r < 4; r++) {
            int idx = tid + r * 256;
            int row = idx >> 2, c4 = (idx & 3) << 2;
            cpasync16(bs + row * 20 + c4, W + (size_t)(n0 + row) * K + k0 + c4);
        }
    };

    load_stage(0, 0);  cp_commit();
    load_stage(1, 16); cp_commit();
    load_stage(2, 32); cp_commit();

    for (int it = 0; it < niter; it++) {
        cp_wait<2>();          // group 'it' complete (it+1, it+2 may be pending)
        __syncthreads();       // data visible to all + all warps done with it-1
        if (it + 3 < niter) load_stage((it + 3) & 3, (it + 3) * 16);
        cp_commit();           // empty commit near the tail keeps counts aligned

        const float* as = sm + (it & 3) * MS_STG;
        const float* bs = as + MS_STGA;
        #pragma unroll
        for (int ks = 0; ks < 2; ks++) {
            unsigned af[4][4], bf[8][2];
            #pragma unroll
            for (int mt = 0; mt < 4; mt++) {
                int mb = wm * 64 + mt * 16 + g;
                af[mt][0] = __float_as_uint(as[(mb)     * 20 + ks * 8 + c]);
                af[mt][1] = __float_as_uint(as[(mb + 8) * 20 + ks * 8 + c]);
                af[mt][2] = __float_as_uint(as[(mb)     * 20 + ks * 8 + c + 4]);
                af[mt][3] = __float_as_uint(as[(mb + 8) * 20 + ks * 8 + c + 4]);
            }
            #pragma unroll
            for (int nt = 0; nt < 8; nt++) {
                int nb = wn * 64 + nt * 8 + g;
                bf[nt][0] = __float_as_uint(bs[nb * 20 + ks * 8 + c]);
                bf[nt][1] = __float_as_uint(bs[nb * 20 + ks * 8 + c + 4]);
            }
            #pragma unroll
            for (int mt = 0; mt < 4; mt++)
                #pragma unroll
                for (int nt = 0; nt < 8; nt++)
                    mma_tf32(acc[mt][nt], af[mt], bf[nt]);
        }
    }

    #pragma unroll
    for (int mt = 0; mt < 4; mt++) {
        int row = m0 + wm * 64 + mt * 16 + g;
        #pragma unroll
        for (int nt = 0; nt < 8; nt++) {
            int col = n0 + wn * 64 + nt * 8 + 2 * c;
            float b0 = bias[col], b1 = bias[col + 1];
            float2 v0 = make_float2(acc[mt][nt][0] + b0, acc[mt][nt][1] + b1);
            float2 v1 = make_float2(acc[mt][nt][2] + b0, acc[mt][nt][3] + b1);
            *(float2*)(C + (size_t)row * N + col)       = v0;
            *(float2*)(C + (size_t)(row + 8) * N + col) = v1;
        }
    }
}

// ---------------- per-(token,head) norm + rope -> q/k/v [H][TOTAL][D] -------
__global__ void qkv_post_kernel(const float* __restrict__ qkvx, const float* __restrict__ qkvy,
                                const float* __restrict__ rcos, const float* __restrict__ rsin,
                                const float* __restrict__ qnx,  const float* __restrict__ knx,
                                const float* __restrict__ qny,  const float* __restrict__ kny,
                                const int* __restrict__ vidx,
                                float* __restrict__ qo, float* __restrict__ ko,
                                float* __restrict__ vo) {
    int i = blockIdx.x, h = blockIdx.y, d = threadIdx.x;
    int src = vidx[i];
    bool isx = src < NX;
    const float* base = isx ? (qkvx + (size_t)src * QKVC)
                            : (qkvy + (size_t)(src - NX) * QKVC);
    float qv = base[h * DD + d];
    float kv = base[DXC + h * DD + d];
    float vv = base[2 * DXC + h * DD + d];

    float qs = qv * qv, ks = kv * kv;
    #pragma unroll
    for (int o = 16; o > 0; o >>= 1) {
        qs += __shfl_xor_sync(0xffffffffu, qs, o);
        ks += __shfl_xor_sync(0xffffffffu, ks, o);
    }
    __shared__ float sq[4], sk[4];
    __shared__ float qsh[DD], ksh[DD];
    int wid = d >> 5;
    if ((d & 31) == 0) { sq[wid] = qs; sk[wid] = ks; }
    __syncthreads();
    float qss = sq[0] + sq[1] + sq[2] + sq[3];
    float kss = sk[0] + sk[1] + sk[2] + sk[3];
    float qn = qv * rsqrtf(qss / (float)DD + 1e-6f) * (isx ? qnx[d] : qny[d]);
    float kn = kv * rsqrtf(kss / (float)DD + 1e-6f) * (isx ? knx[d] : kny[d]);

    if (isx) {
        qsh[d] = qn; ksh[d] = kn;
        __syncthreads();
        int j = d >> 1;
        float cc = rcos[((size_t)src * HH + h) * 64 + j];
        float sn = rsin[((size_t)src * HH + h) * 64 + j];
        if ((d & 1) == 0) {
            qn = qsh[d] * cc - qsh[d + 1] * sn;
            kn = ksh[d] * cc - ksh[d + 1] * sn;
        } else {
            qn = qsh[d - 1] * sn + qsh[d] * cc;
            kn = ksh[d - 1] * sn + ksh[d] * cc;
        }
    }
    size_t o = ((size_t)h * TOTALT + i) * DD + d;
    qo[o] = qn; ko[o] = kn; vo[o] = vv;
}

// ---------------- TF32 tensor-core flash attention ---------------------------
#define AQS 132
#define AVS 68
#define ABQ 128
#define ABK 64

__global__ void __launch_bounds__(256)
attn_mma_kernel(const float* __restrict__ qg, const float* __restrict__ kg,
                const float* __restrict__ vg, const int* __restrict__ vidx,
                float* __restrict__ full) {
    extern __shared__ unsigned asm_[];
    unsigned* Qs = asm_;                    // 128*132
    unsigned* Ks = Qs + ABQ * AQS;          // 64*132
    unsigned* Vt = Ks + ABK * AQS;          // 128*68
    unsigned* Ps = Vt + DD * AVS;           // 128*68

    const int h    = blockIdx.y;
    const int i0   = blockIdx.x * ABQ;
    const int tid  = threadIdx.x;
    const int lane = tid & 31;
    const int warp = tid >> 5;
    const int g    = lane >> 2;
    const int c    = lane & 3;
    const int q4   = lane >> 2;
    const int wr16 = warp * 16;
    const float scale = 0.08838834764831845f;

    const float* qh = qg + (size_t)h * TOTALT * DD;
    const float* kh = kg + (size_t)h * TOTALT * DD;
    const float* vh = vg + (size_t)h * TOTALT * DD;

    #pragma unroll
    for (int it = 0; it < 16; it++) {
        int f = tid + it * 256;
        int row = f >> 5, c4 = (f & 31) << 2;
        int qi = i0 + row; if (qi >= TOTALT) qi = TOTALT - 1;
        float4 t = *(const float4*)(qh + (size_t)qi * DD + c4);
        Qs[row * AQS + c4 + 0] = f2tf32(t.x * scale);
        Qs[row * AQS + c4 + 1] = f2tf32(t.y * scale);
        Qs[row * AQS + c4 + 2] = f2tf32(t.z * scale);
        Qs[row * AQS + c4 + 3] = f2tf32(t.w * scale);
    }

    float o[16][4];
    #pragma unroll
    for (int nt = 0; nt < 16; nt++)
        #pragma unroll
        for (int r = 0; r < 4; r++) o[nt][r] = 0.f;
    float m0 = -1e30f, m1 = -1e30f, l0 = 0.f, l1 = 0.f;

    const int ntiles = (TOTALT + ABK - 1) / ABK;
    for (int t = 0; t < ntiles; t++) {
        const int kb = t * ABK;
        __syncthreads();
        #pragma unroll
        for (int it = 0; it < 8; it++) {
            int f = tid + it * 256;
            int row = f >> 5, c4 = (f & 31) << 2;
            int kidx = kb + row; if (kidx >= TOTALT) kidx = TOTALT - 1;
            float4 tv = *(const float4*)(kh + (size_t)kidx * DD + c4);
            Ks[row * AQS + c4 + 0] = f2tf32(tv.x);
            Ks[row * AQS + c4 + 1] = f2tf32(tv.y);
            Ks[row * AQS + c4 + 2] = f2tf32(tv.z);
            Ks[row * AQS + c4 + 3] = f2tf32(tv.w);
        }
        #pragma unroll
        for (int it = 0; it < 8; it++) {
            int ci = it * 8 + warp;
            int rg = ci & 15;
            int cc = ci >> 4;
            int jb = rg * 4;
            int d0 = cc * 32 + q4 * 4;
            int jrow = kb + jb + c; if (jrow >= TOTALT) jrow = TOTALT - 1;
            float4 tv = *(const float4*)(vh + (size_t)jrow * DD + d0);
            const float* tp = &tv.x;
            #pragma unroll
            for (int ii = 0; ii < 4; ii++) {
                int i = (ii + q4) & 3;
                Vt[(d0 + i) * AVS + jb + c] = f2tf32(tp[i]);
            }
        }
        __syncthreads();

        float s[8][4];
        #pragma unroll
        for (int nt = 0; nt < 8; nt++)
            #pragma unroll
            for (int r = 0; r < 4; r++) s[nt][r] = 0.f;
        #pragma unroll
        for (int ks = 0; ks < 16; ks++) {
            unsigned af[4], bf[8][2];
            int mb = wr16 + g;
            af[0] = Qs[(mb)     * AQS + ks * 8 + c];
            af[1] = Qs[(mb + 8) * AQS + ks * 8 + c];
            af[2] = Qs[(mb)     * AQS + ks * 8 + c + 4];
            af[3] = Qs[(mb + 8) * AQS + ks * 8 + c + 4];
            #pragma unroll
            for (int nt = 0; nt < 8; nt++) {
                bf[nt][0] = Ks[(nt * 8 + g) * AQS + ks * 8 + c];
                bf[nt][1] = Ks[(nt * 8 + g) * AQS + ks * 8 + c + 4];
            }
            #pragma unroll
            for (int nt = 0; nt < 8; nt++)
                mma_tf32(s[nt], af, bf[nt]);
        }

        if (kb + ABK > TOTALT) {
            #pragma unroll
            for (int nt = 0; nt < 8; nt++) {
                int j0 = kb + nt * 8 + 2 * c;
                if (j0     >= TOTALT) { s[nt][0] = -1e30f; s[nt][2] = -1e30f; }
                if (j0 + 1 >= TOTALT) { s[nt][1] = -1e30f; s[nt][3] = -1e30f; }
            }
        }

        float tmax0 = -1e30f, tmax1 = -1e30f;
        #pragma unroll
        for (int nt = 0; nt < 8; nt++) {
            tmax0 = fmaxf(tmax0, fmaxf(s[nt][0], s[nt][1]));
            tmax1 = fmaxf(tmax1, fmaxf(s[nt][2], s[nt][3]));
        }
        tmax0 = fmaxf(tmax0, __shfl_xor_sync(0xffffffffu, tmax0, 1));
        tmax0 = fmaxf(tmax0, __shfl_xor_sync(0xffffffffu, tmax0, 2));
        tmax1 = fmaxf(tmax1, __shfl_xor_sync(0xffffffffu, tmax1, 1));
        tmax1 = fmaxf(tmax1, __shfl_xor_sync(0xffffffffu, tmax1, 2));
        float mn0 = fmaxf(m0, tmax0), mn1 = fmaxf(m1, tmax1);
        float a0 = __expf(m0 - mn0), a1 = __expf(m1 - mn1);
        m0 = mn0; m1 = mn1;

        float ps0 = 0.f, ps1 = 0.f;
        #pragma unroll
        for (int nt = 0; nt < 8; nt++) {
            s[nt][0] = __expf(s[nt][0] - mn0);
            s[nt][1] = __expf(s[nt][1] - mn0);
            s[nt][2] = __expf(s[nt][2] - mn1);
            s[nt][3] = __expf(s[nt][3] - mn1);
            ps0 += s[nt][0] + s[nt][1];
            ps1 += s[nt][2] + s[nt][3];
        }
        ps0 += __shfl_xor_sync(0xffffffffu, ps0, 1);
        ps0 += __shfl_xor_sync(0xffffffffu, ps0, 2);
        ps1 += __shfl_xor_sync(0xffffffffu, ps1, 1);
        ps1 += __shfl_xor_sync(0xffffffffu, ps1, 2);
        l0 = l0 * a0 + ps0;
        l1 = l1 * a1 + ps1;
        #pragma unroll
        for (int nt = 0; nt < 16; nt++) {
            o[nt][0] *= a0; o[nt][1] *= a0;
            o[nt][2] *= a1; o[nt][3] *= a1;
        }

        #pragma unroll
        for (int nt = 0; nt < 8; nt++) {
            *(uint2*)(Ps + (wr16 + g)     * AVS + nt * 8 + 2 * c) =
                make_uint2(f2tf32(s[nt][0]), f2tf32(s[nt][1]));
            *(uint2*)(Ps + (wr16 + g + 8) * AVS + nt * 8 + 2 * c) =
                make_uint2(f2tf32(s[nt][2]), f2tf32(s[nt][3]));
        }
        __syncwarp();

        #pragma unroll
        for (int ks2 = 0; ks2 < 8; ks2++) {
            unsigned af[4];
            af[0] = Ps[(wr16 + g)     * AVS + ks2 * 8 + c];
            af[1] = Ps[(wr16 + g + 8) * AVS + ks2 * 8 + c];
            af[2] = Ps[(wr16 + g)     * AVS + ks2 * 8 + c + 4];
            af[3] = Ps[(wr16 + g + 8) * AVS + ks2 * 8 + c + 4];
            #pragma unroll
            for (int nt2 = 0; nt2 < 16; nt2++) {
                unsigned bf[2];
                bf[0] = Vt[(nt2 * 8 + g) * AVS + ks2 * 8 + c];
                bf[1] = Vt[(nt2 * 8 + g) * AVS + ks2 * 8 + c + 4];
                mma_tf32(o[nt2], af, bf);
            }
        }
    }

    // epilogue: store tf32-rounded (feeds proj GEMMs which round anyway)
    float inv0 = 1.f / l0, inv1 = 1.f / l1;
    int r0 = i0 + wr16 + g, r1 = r0 + 8;
    if (r0 < TOTALT) {
        int dst = vidx[r0];
        float* orow = full + (size_t)dst * DXC + h * DD;
        #pragma unroll
        for (int nt2 = 0; nt2 < 16; nt2++)
            *(uint2*)(orow + nt2 * 8 + 2 * c) =
                make_uint2(f2tf32(o[nt2][0] * inv0), f2tf32(o[nt2][1] * inv0));
    }
    if (r1 < TOTALT) {
        int dst = vidx[r1];
        float* orow = full + (size_t)dst * DXC + h * DD;
        #pragma unroll
        for (int nt2 = 0; nt2 < 16; nt2++)
            *(uint2*)(orow + nt2 * 8 + 2 * c) =
                make_uint2(f2tf32(o[nt2][2] * inv1), f2tf32(o[nt2][3] * inv1));
    }
}

// ---------------- driver ----------------------------------------------------
extern "C" void kernel_launch(void* const* d_in, const int* in_sizes, int n_in,
                              void* d_out, int out_size) {
    const float* x       = (const float*)d_in[0];
    const float* y       = (const float*)d_in[1];
    const float* scale_x = (const float*)d_in[2];
    const float* scale_y = (const float*)d_in[3];
    const float* rcos    = (const float*)d_in[4];
    const float* rsin    = (const float*)d_in[5];
    const float* Wqkvx   = (const float*)d_in[6];
    const float* bqkvx   = (const float*)d_in[7];
    const float* Wqkvy   = (const float*)d_in[8];
    const float* bqkvy   = (const float*)d_in[9];
    const float* qnx     = (const float*)d_in[10];
    const float* knx     = (const float*)d_in[11];
    const float* qny     = (const float*)d_in[12];
    const float* kny     = (const float*)d_in[13];
    const float* Wpx     = (const float*)d_in[14];
    const float* bpx     = (const float*)d_in[15];
    const float* Wpy     = (const float*)d_in[16];
    const float* bpy     = (const float*)d_in[17];
    const int*   vidx    = (const int*)d_in[18];
    float* out = (float*)d_out;

    float *xm, *ym, *qkvx, *qkvy, *q, *k, *v, *full, *wqx, *wpx;
    cudaGetSymbolAddress((void**)&xm,   g_xm);
    cudaGetSymbolAddress((void**)&ym,   g_ym);
    cudaGetSymbolAddress((void**)&qkvx, g_qkvx);
    cudaGetSymbolAddress((void**)&qkvy, g_qkvy);
    cudaGetSymbolAddress((void**)&q,    g_q);
    cudaGetSymbolAddress((void**)&k,    g_k);
    cudaGetSymbolAddress((void**)&v,    g_v);
    cudaGetSymbolAddress((void**)&full, g_full);
    cudaGetSymbolAddress((void**)&wqx,  g_wqx);
    cudaGetSymbolAddress((void**)&wpx,  g_wpx);

    // 0. pre-round the big weights to tf32
    round_tf32_kernel<<<2048, 256>>>(Wqkvx, wqx, 3 * DXC * DXC);
    round_tf32_kernel<<<2048, 256>>>(Wpx,   wpx, DXC * DXC);

    // 1. input rmsnorm + modulation (tf32-rounded outputs)
    rmsnorm_mod_kernel<<<NX, 256>>>(x, scale_x, xm, DXC);
    rmsnorm_mod_kernel<<<LY, 256>>>(y, scale_y, ym, DYC);
    zero_kernel<<<1024, 256>>>(full, (NX + LY) * DXC);

    // 2. qkv projections
    cudaFuncSetAttribute(gemm_tf32_ms, cudaFuncAttributeMaxDynamicSharedMemorySize, MS_SMEM);
    gemm_tf32_ms<<<dim3(QKVC / 256, NX / 128), 256, MS_SMEM>>>(xm, wqx, bqkvx, qkvx, NX, QKVC, DXC);
    gemm_tf32_nt<<<dim3(QKVC / 128, LY / 128), 256>>>(ym, Wqkvy, bqkvy, qkvy, LY, QKVC, DYC);

    // 3. per-head norm + rope, gather valid tokens into [H][TOTAL][D]
    qkv_post_kernel<<<dim3(TOTALT, HH), 128>>>(qkvx, qkvy, rcos, rsin,
                                               qnx, knx, qny, kny, vidx, q, k, v);

    // 4. attention (TF32 tensor cores) -> scatter into full (tf32-rounded)
    const int ATTN_SMEM = (ABQ * AQS + ABK * AQS + DD * AVS + ABQ * AVS) * 4;  // 171008 B
    cudaFuncSetAttribute(attn_mma_kernel, cudaFuncAttributeMaxDynamicSharedMemorySize, ATTN_SMEM);
    attn_mma_kernel<<<dim3((TOTALT + ABQ - 1) / ABQ, HH), 256, ATTN_SMEM>>>(q, k, v, vidx, full);

    // 5. output projections
    gemm_tf32_ms<<<dim3(DXC / 256, NX / 128), 256, MS_SMEM>>>(full, wpx, bpx, out, NX, DXC, DXC);
    gemm_tf32_nt<<<dim3(DYC / 128, LY / 128), 256>>>(full + (size_t)NX * DXC, Wpy, bpy,
                                                     out + (size_t)NX * DXC, LY, DYC, DXC);
}

// round 11
// speedup vs baseline: 3.3793x; 1.1226x over previous
#include <cuda_runtime.h>
#include <cstddef>
#include <cstdint>

#define NX    2048
#define LY    256
#define HH    24
#define DD    128
#define DXC   3072
#define DYC   1536
#define QKVC  9216
#define TOTALT 2248

// ---------------- scratch (static device globals; no allocation) ------------
__device__ float g_xm  [(size_t)NX * DXC];
__device__ float g_ym  [(size_t)LY * DYC];
__device__ float g_qkvx[(size_t)NX * QKVC];
__device__ float g_qkvy[(size_t)LY * QKVC];
__device__ float g_q   [(size_t)HH * TOTALT * DD];
__device__ float g_k   [(size_t)HH * TOTALT * DD];
__device__ float g_v   [(size_t)HH * TOTALT * DD];
__device__ float g_full[(size_t)(NX + LY) * DXC];
__device__ float g_wqx [(size_t)3 * DXC * DXC];   // tf32-rounded weights
__device__ float g_wqy [(size_t)3 * DXC * DYC];
__device__ float g_wpx [(size_t)DXC * DXC];
__device__ float g_wpy [(size_t)DYC * DXC];

// ---------------- helpers ----------------------------------------------------
__device__ __forceinline__ unsigned f2tf32(float f) {
    unsigned r;
    asm("cvt.rna.tf32.f32 %0, %1;" : "=r"(r) : "f"(f));
    return r;
}

__device__ __forceinline__ void mma_tf32(float* d, const unsigned* a, const unsigned* b) {
    asm volatile(
        "mma.sync.aligned.m16n8k8.row.col.f32.tf32.tf32.f32 "
        "{%0,%1,%2,%3}, {%4,%5,%6,%7}, {%8,%9}, {%0,%1,%2,%3};\n"
        : "+f"(d[0]), "+f"(d[1]), "+f"(d[2]), "+f"(d[3])
        : "r"(a[0]), "r"(a[1]), "r"(a[2]), "r"(a[3]), "r"(b[0]), "r"(b[1]));
}

__device__ __forceinline__ void cpasync16(float* dst, const float* src) {
    unsigned d = (unsigned)__cvta_generic_to_shared(dst);
    asm volatile("cp.async.cg.shared.global [%0], [%1], 16;" :: "r"(d), "l"(src));
}
__device__ __forceinline__ void cp_commit() {
    asm volatile("cp.async.commit_group;");
}
template <int N_>
__device__ __forceinline__ void cp_wait() {
    asm volatile("cp.async.wait_group %0;" :: "n"(N_));
}

// ---------------- tf32 rounding pass (weights) -------------------------------
__global__ void round_tf32_kernel(const float* __restrict__ in, float* __restrict__ out, int n) {
    for (int i = blockIdx.x * blockDim.x + threadIdx.x; i < n; i += gridDim.x * blockDim.x)
        out[i] = __uint_as_float(f2tf32(in[i]));
}

// ---------------- rmsnorm * (1 + scale), tf32-rounded output -----------------
__global__ void rmsnorm_mod_kernel(const float* __restrict__ x,
                                   const float* __restrict__ scale,
                                   float* __restrict__ out, int C) {
    int row = blockIdx.x;
    const float* xr = x + (size_t)row * C;
    float ss = 0.f;
    for (int c = threadIdx.x; c < C; c += blockDim.x) { float v = xr[c]; ss += v * v; }
    __shared__ float wsum[8];
    #pragma unroll
    for (int o = 16; o > 0; o >>= 1) ss += __shfl_xor_sync(0xffffffffu, ss, o);
    if ((threadIdx.x & 31) == 0) wsum[threadIdx.x >> 5] = ss;
    __syncthreads();
    float tot = 0.f;
    #pragma unroll
    for (int i = 0; i < 8; i++) tot += wsum[i];
    float r = rsqrtf(tot / (float)C + 1e-6f);
    float* orow = out + (size_t)row * C;
    for (int c = threadIdx.x; c < C; c += blockDim.x)
        orow[c] = __uint_as_float(f2tf32(xr[c] * r * (1.f + scale[c])));
}

// ---------------- zero fill --------------------------------------------------
__global__ void zero_kernel(float* __restrict__ p, int n) {
    for (int i = blockIdx.x * blockDim.x + threadIdx.x; i < n; i += gridDim.x * blockDim.x)
        p[i] = 0.f;
}

// ---------------- dual-part TF32 NT GEMM, 128x256 tiles, BK=32, 3-stage ------
// One launch computes two independent NT GEMMs (x-part and y-part); y blocks
// fill the x-part's tail wave. Inputs pre-rounded to tf32; hot loop is pure
// cp.async + LDS + MMA. 8 warps (2x4), 64x64 warp tiles.
#define DS_ROW  36                       // floats per smem row (32 + pad)
#define DS_A    (128 * DS_ROW)
#define DS_B    (256 * DS_ROW)
#define DS_STG  (DS_A + DS_B)            // 13824 floats
#define DS_SMEM (3 * DS_STG * 4)         // 165888 B

__global__ void __launch_bounds__(256)
gemm_dual(const float* __restrict__ Ax, const float* __restrict__ Wx,
          const float* __restrict__ bx, float* __restrict__ Cx,
          int Nx_, int Kx_,
          const float* __restrict__ Ay, const float* __restrict__ Wy,
          const float* __restrict__ by, float* __restrict__ Cy,
          int Ny_, int Ky_,
          int nbx, int nnx, int nny) {
    extern __shared__ float sm[];
    const int tid  = threadIdx.x;
    const int lane = tid & 31;
    const int warp = tid >> 5;
    const int g    = lane >> 2;
    const int c    = lane & 3;
    const int wm   = warp >> 2;              // 0..1
    const int wn   = warp & 3;               // 0..3

    const float *A, *W, *bias;
    float* C;
    int N, K, m0, n0;
    const int bid = blockIdx.x;
    if (bid < nbx) {
        A = Ax; W = Wx; bias = bx; C = Cx; N = Nx_; K = Kx_;
        m0 = (bid / nnx) * 128; n0 = (bid % nnx) * 256;
    } else {
        int b = bid - nbx;
        A = Ay; W = Wy; bias = by; C = Cy; N = Ny_; K = Ky_;
        m0 = (b / nny) * 128; n0 = (b % nny) * 256;
    }

    float acc[4][8][4];
    #pragma unroll
    for (int mt = 0; mt < 4; mt++)
        #pragma unroll
        for (int nt = 0; nt < 8; nt++)
            #pragma unroll
            for (int r = 0; r < 4; r++) acc[mt][nt][r] = 0.f;

    const int niter = K / 32;

    auto load_stage = [&](int s, int k0) {
        float* as = sm + s * DS_STG;
        float* bs = as + DS_A;
        #pragma unroll
        for (int r = 0; r < 4; r++) {           // A: 128x32 = 1024 f4
            int idx = tid + r * 256;
            int row = idx >> 3, c4 = (idx & 7) << 2;
            cpasync16(as + row * DS_ROW + c4, A + (size_t)(m0 + row) * K + k0 + c4);
        }
        #pragma unroll
        for (int r = 0; r < 8; r++) {           // B: 256x32 = 2048 f4
            int idx = tid + r * 256;
            int row = idx >> 3, c4 = (idx & 7) << 2;
            cpasync16(bs + row * DS_ROW + c4, W + (size_t)(n0 + row) * K + k0 + c4);
        }
    };

    load_stage(0, 0);  cp_commit();
    load_stage(1, 32); cp_commit();

    for (int it = 0; it < niter; it++) {
        cp_wait<1>();
        __syncthreads();
        if (it + 2 < niter) load_stage((it + 2) % 3, (it + 2) * 32);
        cp_commit();                            // empty commit at tail keeps counts aligned

        const float* as = sm + (it % 3) * DS_STG;
        const float* bs = as + DS_A;
        #pragma unroll
        for (int ks = 0; ks < 4; ks++) {
            unsigned af[4][4], bf[8][2];
            #pragma unroll
            for (int mt = 0; mt < 4; mt++) {
                int mb = wm * 64 + mt * 16 + g;
                af[mt][0] = __float_as_uint(as[(mb)     * DS_ROW + ks * 8 + c]);
                af[mt][1] = __float_as_uint(as[(mb + 8) * DS_ROW + ks * 8 + c]);
                af[mt][2] = __float_as_uint(as[(mb)     * DS_ROW + ks * 8 + c + 4]);
                af[mt][3] = __float_as_uint(as[(mb + 8) * DS_ROW + ks * 8 + c + 4]);
            }
            #pragma unroll
            for (int nt = 0; nt < 8; nt++) {
                int nb = wn * 64 + nt * 8 + g;
                bf[nt][0] = __float_as_uint(bs[nb * DS_ROW + ks * 8 + c]);
                bf[nt][1] = __float_as_uint(bs[nb * DS_ROW + ks * 8 + c + 4]);
            }
            #pragma unroll
            for (int mt = 0; mt < 4; mt++)
                #pragma unroll
                for (int nt = 0; nt < 8; nt++)
                    mma_tf32(acc[mt][nt], af[mt], bf[nt]);
        }
        __syncthreads();
    }

    #pragma unroll
    for (int mt = 0; mt < 4; mt++) {
        int row = m0 + wm * 64 + mt * 16 + g;
        #pragma unroll
        for (int nt = 0; nt < 8; nt++) {
            int col = n0 + wn * 64 + nt * 8 + 2 * c;
            float b0 = bias[col], b1 = bias[col + 1];
            float2 v0 = make_float2(acc[mt][nt][0] + b0, acc[mt][nt][1] + b1);
            float2 v1 = make_float2(acc[mt][nt][2] + b0, acc[mt][nt][3] + b1);
            *(float2*)(C + (size_t)row * N + col)       = v0;
            *(float2*)(C + (size_t)(row + 8) * N + col) = v1;
        }
    }
}

// ---------------- per-(token,head) norm + rope -> q/k/v [H][TOTAL][D] -------
__global__ void qkv_post_kernel(const float* __restrict__ qkvx, const float* __restrict__ qkvy,
                                const float* __restrict__ rcos, const float* __restrict__ rsin,
                                const float* __restrict__ qnx,  const float* __restrict__ knx,
                                const float* __restrict__ qny,  const float* __restrict__ kny,
                                const int* __restrict__ vidx,
                                float* __restrict__ qo, float* __restrict__ ko,
                                float* __restrict__ vo) {
    int i = blockIdx.x, h = blockIdx.y, d = threadIdx.x;
    int src = vidx[i];
    bool isx = src < NX;
    const float* base = isx ? (qkvx + (size_t)src * QKVC)
                            : (qkvy + (size_t)(src - NX) * QKVC);
    float qv = base[h * DD + d];
    float kv = base[DXC + h * DD + d];
    float vv = base[2 * DXC + h * DD + d];

    float qs = qv * qv, ks = kv * kv;
    #pragma unroll
    for (int o = 16; o > 0; o >>= 1) {
        qs += __shfl_xor_sync(0xffffffffu, qs, o);
        ks += __shfl_xor_sync(0xffffffffu, ks, o);
    }
    __shared__ float sq[4], sk[4];
    __shared__ float qsh[DD], ksh[DD];
    int wid = d >> 5;
    if ((d & 31) == 0) { sq[wid] = qs; sk[wid] = ks; }
    __syncthreads();
    float qss = sq[0] + sq[1] + sq[2] + sq[3];
    float kss = sk[0] + sk[1] + sk[2] + sk[3];
    float qn = qv * rsqrtf(qss / (float)DD + 1e-6f) * (isx ? qnx[d] : qny[d]);
    float kn = kv * rsqrtf(kss / (float)DD + 1e-6f) * (isx ? knx[d] : kny[d]);

    if (isx) {
        qsh[d] = qn; ksh[d] = kn;
        __syncthreads();
        int j = d >> 1;
        float cc = rcos[((size_t)src * HH + h) * 64 + j];
        float sn = rsin[((size_t)src * HH + h) * 64 + j];
        if ((d & 1) == 0) {
            qn = qsh[d] * cc - qsh[d + 1] * sn;
            kn = ksh[d] * cc - ksh[d + 1] * sn;
        } else {
            qn = qsh[d - 1] * sn + qsh[d] * cc;
            kn = ksh[d - 1] * sn + ksh[d] * cc;
        }
    }
    size_t o = ((size_t)h * TOTALT + i) * DD + d;
    qo[o] = qn; ko[o] = kn; vo[o] = vv;
}

// ---------------- TF32 tensor-core flash attention ---------------------------
#define AQS 132
#define AVS 68
#define ABQ 128
#define ABK 64

__global__ void __launch_bounds__(256)
attn_mma_kernel(const float* __restrict__ qg, const float* __restrict__ kg,
                const float* __restrict__ vg, const int* __restrict__ vidx,
                float* __restrict__ full) {
    extern __shared__ unsigned asm_[];
    unsigned* Qs = asm_;                    // 128*132
    unsigned* Ks = Qs + ABQ * AQS;          // 64*132
    unsigned* Vt = Ks + ABK * AQS;          // 128*68
    unsigned* Ps = Vt + DD * AVS;           // 128*68

    const int h    = blockIdx.y;
    const int i0   = blockIdx.x * ABQ;
    const int tid  = threadIdx.x;
    const int lane = tid & 31;
    const int warp = tid >> 5;
    const int g    = lane >> 2;
    const int c    = lane & 3;
    const int q4   = lane >> 2;
    const int wr16 = warp * 16;
    const float scale = 0.08838834764831845f;

    const float* qh = qg + (size_t)h * TOTALT * DD;
    const float* kh = kg + (size_t)h * TOTALT * DD;
    const float* vh = vg + (size_t)h * TOTALT * DD;

    #pragma unroll
    for (int it = 0; it < 16; it++) {
        int f = tid + it * 256;
        int row = f >> 5, c4 = (f & 31) << 2;
        int qi = i0 + row; if (qi >= TOTALT) qi = TOTALT - 1;
        float4 t = *(const float4*)(qh + (size_t)qi * DD + c4);
        Qs[row * AQS + c4 + 0] = f2tf32(t.x * scale);
        Qs[row * AQS + c4 + 1] = f2tf32(t.y * scale);
        Qs[row * AQS + c4 + 2] = f2tf32(t.z * scale);
        Qs[row * AQS + c4 + 3] = f2tf32(t.w * scale);
    }

    float o[16][4];
    #pragma unroll
    for (int nt = 0; nt < 16; nt++)
        #pragma unroll
        for (int r = 0; r < 4; r++) o[nt][r] = 0.f;
    float m0 = -1e30f, m1 = -1e30f, l0 = 0.f, l1 = 0.f;

    const int ntiles = (TOTALT + ABK - 1) / ABK;
    for (int t = 0; t < ntiles; t++) {
        const int kb = t * ABK;
        __syncthreads();
        #pragma unroll
        for (int it = 0; it < 8; it++) {
            int f = tid + it * 256;
            int row = f >> 5, c4 = (f & 31) << 2;
            int kidx = kb + row; if (kidx >= TOTALT) kidx = TOTALT - 1;
            float4 tv = *(const float4*)(kh + (size_t)kidx * DD + c4);
            Ks[row * AQS + c4 + 0] = f2tf32(tv.x);
            Ks[row * AQS + c4 + 1] = f2tf32(tv.y);
            Ks[row * AQS + c4 + 2] = f2tf32(tv.z);
            Ks[row * AQS + c4 + 3] = f2tf32(tv.w);
        }
        #pragma unroll
        for (int it = 0; it < 8; it++) {
            int ci = it * 8 + warp;
            int rg = ci & 15;
            int cc = ci >> 4;
            int jb = rg * 4;
            int d0 = cc * 32 + q4 * 4;
            int jrow = kb + jb + c; if (jrow >= TOTALT) jrow = TOTALT - 1;
            float4 tv = *(const float4*)(vh + (size_t)jrow * DD + d0);
            const float* tp = &tv.x;
            #pragma unroll
            for (int ii = 0; ii < 4; ii++) {
                int i = (ii + q4) & 3;
                Vt[(d0 + i) * AVS + jb + c] = f2tf32(tp[i]);
            }
        }
        __syncthreads();

        float s[8][4];
        #pragma unroll
        for (int nt = 0; nt < 8; nt++)
            #pragma unroll
            for (int r = 0; r < 4; r++) s[nt][r] = 0.f;
        #pragma unroll
        for (int ks = 0; ks < 16; ks++) {
            unsigned af[4], bf[8][2];
            int mb = wr16 + g;
            af[0] = Qs[(mb)     * AQS + ks * 8 + c];
            af[1] = Qs[(mb + 8) * AQS + ks * 8 + c];
            af[2] = Qs[(mb)     * AQS + ks * 8 + c + 4];
            af[3] = Qs[(mb + 8) * AQS + ks * 8 + c + 4];
            #pragma unroll
            for (int nt = 0; nt < 8; nt++) {
                bf[nt][0] = Ks[(nt * 8 + g) * AQS + ks * 8 + c];
                bf[nt][1] = Ks[(nt * 8 + g) * AQS + ks * 8 + c + 4];
            }
            #pragma unroll
            for (int nt = 0; nt < 8; nt++)
                mma_tf32(s[nt], af, bf[nt]);
        }

        if (kb + ABK > TOTALT) {
            #pragma unroll
            for (int nt = 0; nt < 8; nt++) {
                int j0 = kb + nt * 8 + 2 * c;
                if (j0     >= TOTALT) { s[nt][0] = -1e30f; s[nt][2] = -1e30f; }
                if (j0 + 1 >= TOTALT) { s[nt][1] = -1e30f; s[nt][3] = -1e30f; }
            }
        }

        float tmax0 = -1e30f, tmax1 = -1e30f;
        #pragma unroll
        for (int nt = 0; nt < 8; nt++) {
            tmax0 = fmaxf(tmax0, fmaxf(s[nt][0], s[nt][1]));
            tmax1 = fmaxf(tmax1, fmaxf(s[nt][2], s[nt][3]));
        }
        tmax0 = fmaxf(tmax0, __shfl_xor_sync(0xffffffffu, tmax0, 1));
        tmax0 = fmaxf(tmax0, __shfl_xor_sync(0xffffffffu, tmax0, 2));
        tmax1 = fmaxf(tmax1, __shfl_xor_sync(0xffffffffu, tmax1, 1));
        tmax1 = fmaxf(tmax1, __shfl_xor_sync(0xffffffffu, tmax1, 2));
        float mn0 = fmaxf(m0, tmax0), mn1 = fmaxf(m1, tmax1);
        float a0 = __expf(m0 - mn0), a1 = __expf(m1 - mn1);
        m0 = mn0; m1 = mn1;

        float ps0 = 0.f, ps1 = 0.f;
        #pragma unroll
        for (int nt = 0; nt < 8; nt++) {
            s[nt][0] = __expf(s[nt][0] - mn0);
            s[nt][1] = __expf(s[nt][1] - mn0);
            s[nt][2] = __expf(s[nt][2] - mn1);
            s[nt][3] = __expf(s[nt][3] - mn1);
            ps0 += s[nt][0] + s[nt][1];
            ps1 += s[nt][2] + s[nt][3];
        }
        ps0 += __shfl_xor_sync(0xffffffffu, ps0, 1);
        ps0 += __shfl_xor_sync(0xffffffffu, ps0, 2);
        ps1 += __shfl_xor_sync(0xffffffffu, ps1, 1);
        ps1 += __shfl_xor_sync(0xffffffffu, ps1, 2);
        l0 = l0 * a0 + ps0;
        l1 = l1 * a1 + ps1;
        #pragma unroll
        for (int nt = 0; nt < 16; nt++) {
            o[nt][0] *= a0; o[nt][1] *= a0;
            o[nt][2] *= a1; o[nt][3] *= a1;
        }

        #pragma unroll
        for (int nt = 0; nt < 8; nt++) {
            *(uint2*)(Ps + (wr16 + g)     * AVS + nt * 8 + 2 * c) =
                make_uint2(f2tf32(s[nt][0]), f2tf32(s[nt][1]));
            *(uint2*)(Ps + (wr16 + g + 8) * AVS + nt * 8 + 2 * c) =
                make_uint2(f2tf32(s[nt][2]), f2tf32(s[nt][3]));
        }
        __syncwarp();

        #pragma unroll
        for (int ks2 = 0; ks2 < 8; ks2++) {
            unsigned af[4];
            af[0] = Ps[(wr16 + g)     * AVS + ks2 * 8 + c];
            af[1] = Ps[(wr16 + g + 8) * AVS + ks2 * 8 + c];
            af[2] = Ps[(wr16 + g)     * AVS + ks2 * 8 + c + 4];
            af[3] = Ps[(wr16 + g + 8) * AVS + ks2 * 8 + c + 4];
            #pragma unroll
            for (int nt2 = 0; nt2 < 16; nt2++) {
                unsigned bf[2];
                bf[0] = Vt[(nt2 * 8 + g) * AVS + ks2 * 8 + c];
                bf[1] = Vt[(nt2 * 8 + g) * AVS + ks2 * 8 + c + 4];
                mma_tf32(o[nt2], af, bf);
            }
        }
    }

    // epilogue: store tf32-rounded (feeds proj GEMMs which need rounded input)
    float inv0 = 1.f / l0, inv1 = 1.f / l1;
    int r0 = i0 + wr16 + g, r1 = r0 + 8;
    if (r0 < TOTALT) {
        int dst = vidx[r0];
        float* orow = full + (size_t)dst * DXC + h * DD;
        #pragma unroll
        for (int nt2 = 0; nt2 < 16; nt2++)
            *(uint2*)(orow + nt2 * 8 + 2 * c) =
                make_uint2(f2tf32(o[nt2][0] * inv0), f2tf32(o[nt2][1] * inv0));
    }
    if (r1 < TOTALT) {
        int dst = vidx[r1];
        float* orow = full + (size_t)dst * DXC + h * DD;
        #pragma unroll
        for (int nt2 = 0; nt2 < 16; nt2++)
            *(uint2*)(orow + nt2 * 8 + 2 * c) =
                make_uint2(f2tf32(o[nt2][2] * inv1), f2tf32(o[nt2][3] * inv1));
    }
}

// ---------------- driver ----------------------------------------------------
extern "C" void kernel_launch(void* const* d_in, const int* in_sizes, int n_in,
                              void* d_out, int out_size) {
    const float* x       = (const float*)d_in[0];
    const float* y       = (const float*)d_in[1];
    const float* scale_x = (const float*)d_in[2];
    const float* scale_y = (const float*)d_in[3];
    const float* rcos    = (const float*)d_in[4];
    const float* rsin    = (const float*)d_in[5];
    const float* Wqkvx   = (const float*)d_in[6];
    const float* bqkvx   = (const float*)d_in[7];
    const float* Wqkvy   = (const float*)d_in[8];
    const float* bqkvy   = (const float*)d_in[9];
    const float* qnx     = (const float*)d_in[10];
    const float* knx     = (const float*)d_in[11];
    const float* qny     = (const float*)d_in[12];
    const float* kny     = (const float*)d_in[13];
    const float* Wpx     = (const float*)d_in[14];
    const float* bpx     = (const float*)d_in[15];
    const float* Wpy     = (const float*)d_in[16];
    const float* bpy     = (const float*)d_in[17];
    const int*   vidx    = (const int*)d_in[18];
    float* out = (float*)d_out;

    float *xm, *ym, *qkvx, *qkvy, *q, *k, *v, *full, *wqx, *wqy, *wpx, *wpy;
    cudaGetSymbolAddress((void**)&xm,   g_xm);
    cudaGetSymbolAddress((void**)&ym,   g_ym);
    cudaGetSymbolAddress((void**)&qkvx, g_qkvx);
    cudaGetSymbolAddress((void**)&qkvy, g_qkvy);
    cudaGetSymbolAddress((void**)&q,    g_q);
    cudaGetSymbolAddress((void**)&k,    g_k);
    cudaGetSymbolAddress((void**)&v,    g_v);
    cudaGetSymbolAddress((void**)&full, g_full);
    cudaGetSymbolAddress((void**)&wqx,  g_wqx);
    cudaGetSymbolAddress((void**)&wqy,  g_wqy);
    cudaGetSymbolAddress((void**)&wpx,  g_wpx);
    cudaGetSymbolAddress((void**)&wpy,  g_wpy);

    // 0. pre-round all weights to tf32
    round_tf32_kernel<<<2048, 256>>>(Wqkvx, wqx, 3 * DXC * DXC);
    round_tf32_kernel<<<1024, 256>>>(Wqkvy, wqy, 3 * DXC * DYC);
    round_tf32_kernel<<<1024, 256>>>(Wpx,   wpx, DXC * DXC);
    round_tf32_kernel<<<512,  256>>>(Wpy,   wpy, DYC * DXC);

    // 1. input rmsnorm + modulation (tf32-rounded outputs)
    rmsnorm_mod_kernel<<<NX, 256>>>(x, scale_x, xm, DXC);
    rmsnorm_mod_kernel<<<LY, 256>>>(y, scale_y, ym, DYC);
    zero_kernel<<<1024, 256>>>(full, (NX + LY) * DXC);

    // 2. qkv projections — x and y fused in one launch
    cudaFuncSetAttribute(gemm_dual, cudaFuncAttributeMaxDynamicSharedMemorySize, DS_SMEM);
    {
        const int nbx = (NX / 128) * (QKVC / 256);   // 576
        const int nby = (LY / 128) * (QKVC / 256);   // 72
        gemm_dual<<<nbx + nby, 256, DS_SMEM>>>(
            xm, wqx, bqkvx, qkvx, QKVC, DXC,
            ym, wqy, bqkvy, qkvy, QKVC, DYC,
            nbx, QKVC / 256, QKVC / 256);
    }

    // 3. per-head norm + rope, gather valid tokens into [H][TOTAL][D]
    qkv_post_kernel<<<dim3(TOTALT, HH), 128>>>(qkvx, qkvy, rcos, rsin,
                                               qnx, knx, qny, kny, vidx, q, k, v);

    // 4. attention (TF32 tensor cores) -> scatter into full (tf32-rounded)
    const int ATTN_SMEM = (ABQ * AQS + ABK * AQS + DD * AVS + ABQ * AVS) * 4;  // 171008 B
    cudaFuncSetAttribute(attn_mma_kernel, cudaFuncAttributeMaxDynamicSharedMemorySize, ATTN_SMEM);
    attn_mma_kernel<<<dim3((TOTALT + ABQ - 1) / ABQ, HH), 256, ATTN_SMEM>>>(q, k, v, vidx, full);

    // 5. output projections — x and y fused in one launch
    {
        const int nbx = (NX / 128) * (DXC / 256);    // 192
        const int nby = (LY / 128) * (DYC / 256);    // 12
        gemm_dual<<<nbx + nby, 256, DS_SMEM>>>(
            full, wpx, bpx, out, DXC, DXC,
            full + (size_t)NX * DXC, wpy, bpy, out + (size_t)NX * DXC, DYC, DXC,
            nbx, DXC / 256, DYC / 256);
    }
}

// round 13
// speedup vs baseline: 3.4483x; 1.0204x over previous
#include <cuda_runtime.h>
#include <cstddef>
#include <cstdint>

#define NX    2048
#define LY    256
#define HH    24
#define DD    128
#define DXC   3072
#define DYC   1536
#define QKVC  9216
#define TOTALT 2248

// ---------------- scratch (static device globals; no allocation) ------------
__device__ float g_xm  [(size_t)NX * DXC];
__device__ float g_ym  [(size_t)LY * DYC];
__device__ float g_qkvx[(size_t)NX * QKVC];
__device__ float g_qkvy[(size_t)LY * QKVC];
__device__ float g_q   [(size_t)HH * TOTALT * DD];
__device__ float g_k   [(size_t)HH * TOTALT * DD];
__device__ float g_v   [(size_t)HH * TOTALT * DD];
__device__ float g_full[(size_t)(NX + LY) * DXC];
__device__ float g_wqx [(size_t)3 * DXC * DXC];   // tf32-rounded weights
__device__ float g_wqy [(size_t)3 * DXC * DYC];
__device__ float g_wpx [(size_t)DXC * DXC];
__device__ float g_wpy [(size_t)DYC * DXC];

// ---------------- helpers ----------------------------------------------------
__device__ __forceinline__ unsigned f2tf32(float f) {
    unsigned r;
    asm("cvt.rna.tf32.f32 %0, %1;" : "=r"(r) : "f"(f));
    return r;
}

__device__ __forceinline__ void mma_tf32(float* d, const unsigned* a, const unsigned* b) {
    asm volatile(
        "mma.sync.aligned.m16n8k8.row.col.f32.tf32.tf32.f32 "
        "{%0,%1,%2,%3}, {%4,%5,%6,%7}, {%8,%9}, {%0,%1,%2,%3};\n"
        : "+f"(d[0]), "+f"(d[1]), "+f"(d[2]), "+f"(d[3])
        : "r"(a[0]), "r"(a[1]), "r"(a[2]), "r"(a[3]), "r"(b[0]), "r"(b[1]));
}

__device__ __forceinline__ void cpasync16(float* dst, const float* src) {
    unsigned d = (unsigned)__cvta_generic_to_shared(dst);
    asm volatile("cp.async.cg.shared.global [%0], [%1], 16;" :: "r"(d), "l"(src));
}
__device__ __forceinline__ void cp_commit() {
    asm volatile("cp.async.commit_group;");
}
template <int N_>
__device__ __forceinline__ void cp_wait() {
    asm volatile("cp.async.wait_group %0;" :: "n"(N_));
}

// ---------------- fused tf32 rounding pass (all 4 weight tensors) ------------
__global__ void round4_kernel(const float4* __restrict__ i0, float4* __restrict__ o0, int n0,
                              const float4* __restrict__ i1, float4* __restrict__ o1, int n1,
                              const float4* __restrict__ i2, float4* __restrict__ o2, int n2,
                              const float4* __restrict__ i3, float4* __restrict__ o3, int n3) {
    const int total = n0 + n1 + n2 + n3;
    for (int i = blockIdx.x * blockDim.x + threadIdx.x; i < total; i += gridDim.x * blockDim.x) {
        const float4* src;
        float4* dst;
        int j = i;
        if (j < n0) { src = i0; dst = o0; }
        else if ((j -= n0) < n1) { src = i1; dst = o1; }
        else if ((j -= n1) < n2) { src = i2; dst = o2; }
        else { j -= n2; src = i3; dst = o3; }
        float4 v = src[j];
        v.x = __uint_as_float(f2tf32(v.x));
        v.y = __uint_as_float(f2tf32(v.y));
        v.z = __uint_as_float(f2tf32(v.z));
        v.w = __uint_as_float(f2tf32(v.w));
        dst[j] = v;
    }
}

// ---------------- rmsnorm * (1 + scale), tf32-rounded output -----------------
__global__ void rmsnorm_mod_kernel(const float* __restrict__ x,
                                   const float* __restrict__ scale,
                                   float* __restrict__ out, int C) {
    int row = blockIdx.x;
    const float* xr = x + (size_t)row * C;
    float ss = 0.f;
    for (int c = threadIdx.x; c < C; c += blockDim.x) { float v = xr[c]; ss += v * v; }
    __shared__ float wsum[8];
    #pragma unroll
    for (int o = 16; o > 0; o >>= 1) ss += __shfl_xor_sync(0xffffffffu, ss, o);
    if ((threadIdx.x & 31) == 0) wsum[threadIdx.x >> 5] = ss;
    __syncthreads();
    float tot = 0.f;
    #pragma unroll
    for (int i = 0; i < 8; i++) tot += wsum[i];
    float r = rsqrtf(tot / (float)C + 1e-6f);
    float* orow = out + (size_t)row * C;
    for (int c = threadIdx.x; c < C; c += blockDim.x)
        orow[c] = __uint_as_float(f2tf32(xr[c] * r * (1.f + scale[c])));
}

// ---------------- zero fill --------------------------------------------------
__global__ void zero_kernel(float* __restrict__ p, int n) {
    for (int i = blockIdx.x * blockDim.x + threadIdx.x; i < n; i += gridDim.x * blockDim.x)
        p[i] = 0.f;
}

// ---------------- dual-part TF32 NT GEMM, 128x256 tiles, BK=64, 2-stage ------
// One launch computes two independent NT GEMMs (x and y parts). Inputs
// pre-rounded to tf32; hot loop is pure cp.async + LDS + MMA. 8 warps (2x4),
// 64x64 warp tiles. BK=64 halves barrier frequency vs BK=32.
#define DS_ROW  68                       // floats per smem row (64 + pad); 68 % 32 == 4
#define DS_A    (128 * DS_ROW)
#define DS_B    (256 * DS_ROW)
#define DS_STG  (DS_A + DS_B)            // 26112 floats
#define DS_SMEM (2 * DS_STG * 4)         // 208896 B

__global__ void __launch_bounds__(256)
gemm_dual(const float* __restrict__ Ax, const float* __restrict__ Wx,
          const float* __restrict__ bx, float* __restrict__ Cx,
          int Nx_, int Kx_,
          const float* __restrict__ Ay, const float* __restrict__ Wy,
          const float* __restrict__ by, float* __restrict__ Cy,
          int Ny_, int Ky_,
          int nbx, int nnx, int nny) {
    extern __shared__ float sm[];
    const int tid  = threadIdx.x;
    const int lane = tid & 31;
    const int warp = tid >> 5;
    const int g    = lane >> 2;
    const int c    = lane & 3;
    const int wm   = warp >> 2;              // 0..1
    const int wn   = warp & 3;               // 0..3

    const float *A, *W, *bias;
    float* C;
    int N, K, m0, n0;
    const int bid = blockIdx.x;
    if (bid < nbx) {
        A = Ax; W = Wx; bias = bx; C = Cx; N = Nx_; K = Kx_;
        m0 = (bid / nnx) * 128; n0 = (bid % nnx) * 256;
    } else {
        int b = bid - nbx;
        A = Ay; W = Wy; bias = by; C = Cy; N = Ny_; K = Ky_;
        m0 = (b / nny) * 128; n0 = (b % nny) * 256;
    }

    float acc[4][8][4];
    #pragma unroll
    for (int mt = 0; mt < 4; mt++)
        #pragma unroll
        for (int nt = 0; nt < 8; nt++)
            #pragma unroll
            for (int r = 0; r < 4; r++) acc[mt][nt][r] = 0.f;

    const int niter = K / 64;

    auto load_stage = [&](int s, int k0) {
        float* as = sm + s * DS_STG;
        float* bs = as + DS_A;
        #pragma unroll
        for (int r = 0; r < 8; r++) {           // A: 128 rows x 16 chunks = 2048
            int idx = tid + r * 256;
            int row = idx >> 4, c4 = (idx & 15) << 2;
            cpasync16(as + row * DS_ROW + c4, A + (size_t)(m0 + row) * K + k0 + c4);
        }
        #pragma unroll
        for (int r = 0; r < 16; r++) {          // B: 256 rows x 16 chunks = 4096
            int idx = tid + r * 256;
            int row = idx >> 4, c4 = (idx & 15) << 2;
            cpasync16(bs + row * DS_ROW + c4, W + (size_t)(n0 + row) * K + k0 + c4);
        }
    };

    load_stage(0, 0);  cp_commit();
    load_stage(1, 64); cp_commit();

    for (int it = 0; it < niter; it++) {
        cp_wait<1>();
        __syncthreads();

        const float* as = sm + (it & 1) * DS_STG;
        const float* bs = as + DS_A;
        #pragma unroll
        for (int ks = 0; ks < 8; ks++) {
            unsigned af[4][4], bf[8][2];
            #pragma unroll
            for (int mt = 0; mt < 4; mt++) {
                int mb = wm * 64 + mt * 16 + g;
                af[mt][0] = __float_as_uint(as[(mb)     * DS_ROW + ks * 8 + c]);
                af[mt][1] = __float_as_uint(as[(mb + 8) * DS_ROW + ks * 8 + c]);
                af[mt][2] = __float_as_uint(as[(mb)     * DS_ROW + ks * 8 + c + 4]);
                af[mt][3] = __float_as_uint(as[(mb + 8) * DS_ROW + ks * 8 + c + 4]);
            }
            #pragma unroll
            for (int nt = 0; nt < 8; nt++) {
                int nb = wn * 64 + nt * 8 + g;
                bf[nt][0] = __float_as_uint(bs[nb * DS_ROW + ks * 8 + c]);
                bf[nt][1] = __float_as_uint(bs[nb * DS_ROW + ks * 8 + c + 4]);
            }
            #pragma unroll
            for (int mt = 0; mt < 4; mt++)
                #pragma unroll
                for (int nt = 0; nt < 8; nt++)
                    mma_tf32(acc[mt][nt], af[mt], bf[nt]);
        }
        __syncthreads();
        if (it + 2 < niter) load_stage(it & 1, (it + 2) * 64);
        cp_commit();                             // unconditional: keeps group count aligned
    }

    #pragma unroll
    for (int mt = 0; mt < 4; mt++) {
        int row = m0 + wm * 64 + mt * 16 + g;
        #pragma unroll
        for (int nt = 0; nt < 8; nt++) {
            int col = n0 + wn * 64 + nt * 8 + 2 * c;
            float b0 = bias[col], b1 = bias[col + 1];
            float2 v0 = make_float2(acc[mt][nt][0] + b0, acc[mt][nt][1] + b1);
            float2 v1 = make_float2(acc[mt][nt][2] + b0, acc[mt][nt][3] + b1);
            *(float2*)(C + (size_t)row * N + col)       = v0;
            *(float2*)(C + (size_t)(row + 8) * N + col) = v1;
        }
    }
}

// ---------------- per-(token,head) norm + rope -> q/k/v [H][TOTAL][D] -------
__global__ void qkv_post_kernel(const float* __restrict__ qkvx, const float* __restrict__ qkvy,
                                const float* __restrict__ rcos, const float* __restrict__ rsin,
                                const float* __restrict__ qnx,  const float* __restrict__ knx,
                                const float* __restrict__ qny,  const float* __restrict__ kny,
                                const int* __restrict__ vidx,
                                float* __restrict__ qo, float* __restrict__ ko,
                                float* __restrict__ vo) {
    int i = blockIdx.x, h = blockIdx.y, d = threadIdx.x;
    int src = vidx[i];
    bool isx = src < NX;
    const float* base = isx ? (qkvx + (size_t)src * QKVC)
                            : (qkvy + (size_t)(src - NX) * QKVC);
    float qv = base[h * DD + d];
    float kv = base[DXC + h * DD + d];
    float vv = base[2 * DXC + h * DD + d];

    float qs = qv * qv, ks = kv * kv;
    #pragma unroll
    for (int o = 16; o > 0; o >>= 1) {
        qs += __shfl_xor_sync(0xffffffffu, qs, o);
        ks += __shfl_xor_sync(0xffffffffu, ks, o);
    }
    __shared__ float sq[4], sk[4];
    __shared__ float qsh[DD], ksh[DD];
    int wid = d >> 5;
    if ((d & 31) == 0) { sq[wid] = qs; sk[wid] = ks; }
    __syncthreads();
    float qss = sq[0] + sq[1] + sq[2] + sq[3];
    float kss = sk[0] + sk[1] + sk[2] + sk[3];
    float qn = qv * rsqrtf(qss / (float)DD + 1e-6f) * (isx ? qnx[d] : qny[d]);
    float kn = kv * rsqrtf(kss / (float)DD + 1e-6f) * (isx ? knx[d] : kny[d]);

    if (isx) {
        qsh[d] = qn; ksh[d] = kn;
        __syncthreads();
        int j = d >> 1;
        float cc = rcos[((size_t)src * HH + h) * 64 + j];
        float sn = rsin[((size_t)src * HH + h) * 64 + j];
        if ((d & 1) == 0) {
            qn = qsh[d] * cc - qsh[d + 1] * sn;
            kn = ksh[d] * cc - ksh[d + 1] * sn;
        } else {
            qn = qsh[d - 1] * sn + qsh[d] * cc;
            kn = ksh[d - 1] * sn + ksh[d] * cc;
        }
    }
    size_t o = ((size_t)h * TOTALT + i) * DD + d;
    qo[o] = qn; ko[o] = kn; vo[o] = vv;
}

// ---------------- TF32 tensor-core flash attention ---------------------------
#define AQS 132
#define AVS 68
#define ABQ 128
#define ABK 64

__global__ void __launch_bounds__(256)
attn_mma_kernel(const float* __restrict__ qg, const float* __restrict__ kg,
                const float* __restrict__ vg, const int* __restrict__ vidx,
                float* __restrict__ full) {
    extern __shared__ unsigned asm_[];
    unsigned* Qs = asm_;                    // 128*132
    unsigned* Ks = Qs + ABQ * AQS;          // 64*132
    unsigned* Vt = Ks + ABK * AQS;          // 128*68
    unsigned* Ps = Vt + DD * AVS;           // 128*68

    const int h    = blockIdx.y;
    const int i0   = blockIdx.x * ABQ;
    const int tid  = threadIdx.x;
    const int lane = tid & 31;
    const int warp = tid >> 5;
    const int g    = lane >> 2;
    const int c    = lane & 3;
    const int q4   = lane >> 2;
    const int wr16 = warp * 16;
    const float scale = 0.08838834764831845f;

    const float* qh = qg + (size_t)h * TOTALT * DD;
    const float* kh = kg + (size_t)h * TOTALT * DD;
    const float* vh = vg + (size_t)h * TOTALT * DD;

    #pragma unroll
    for (int it = 0; it < 16; it++) {
        int f = tid + it * 256;
        int row = f >> 5, c4 = (f & 31) << 2;
        int qi = i0 + row; if (qi >= TOTALT) qi = TOTALT - 1;
        float4 t = *(const float4*)(qh + (size_t)qi * DD + c4);
        Qs[row * AQS + c4 + 0] = f2tf32(t.x * scale);
        Qs[row * AQS + c4 + 1] = f2tf32(t.y * scale);
        Qs[row * AQS + c4 + 2] = f2tf32(t.z * scale);
        Qs[row * AQS + c4 + 3] = f2tf32(t.w * scale);
    }

    float o[16][4];
    #pragma unroll
    for (int nt = 0; nt < 16; nt++)
        #pragma unroll
        for (int r = 0; r < 4; r++) o[nt][r] = 0.f;
    float m0 = -1e30f, m1 = -1e30f, l0 = 0.f, l1 = 0.f;

    const int ntiles = (TOTALT + ABK - 1) / ABK;
    for (int t = 0; t < ntiles; t++) {
        const int kb = t * ABK;
        __syncthreads();
        #pragma unroll
        for (int it = 0; it < 8; it++) {
            int f = tid + it * 256;
            int row = f >> 5, c4 = (f & 31) << 2;
            int kidx = kb + row; if (kidx >= TOTALT) kidx = TOTALT - 1;
            float4 tv = *(const float4*)(kh + (size_t)kidx * DD + c4);
            Ks[row * AQS + c4 + 0] = f2tf32(tv.x);
            Ks[row * AQS + c4 + 1] = f2tf32(tv.y);
            Ks[row * AQS + c4 + 2] = f2tf32(tv.z);
            Ks[row * AQS + c4 + 3] = f2tf32(tv.w);
        }
        #pragma unroll
        for (int it = 0; it < 8; it++) {
            int ci = it * 8 + warp;
            int rg = ci & 15;
            int cc = ci >> 4;
            int jb = rg * 4;
            int d0 = cc * 32 + q4 * 4;
            int jrow = kb + jb + c; if (jrow >= TOTALT) jrow = TOTALT - 1;
            float4 tv = *(const float4*)(vh + (size_t)jrow * DD + d0);
            const float* tp = &tv.x;
            #pragma unroll
            for (int ii = 0; ii < 4; ii++) {
                int i = (ii + q4) & 3;
                Vt[(d0 + i) * AVS + jb + c] = f2tf32(tp[i]);
            }
        }
        __syncthreads();

        float s[8][4];
        #pragma unroll
        for (int nt = 0; nt < 8; nt++)
            #pragma unroll
            for (int r = 0; r < 4; r++) s[nt][r] = 0.f;
        #pragma unroll
        for (int ks = 0; ks < 16; ks++) {
            unsigned af[4], bf[8][2];
            int mb = wr16 + g;
            af[0] = Qs[(mb)     * AQS + ks * 8 + c];
            af[1] = Qs[(mb + 8) * AQS + ks * 8 + c];
            af[2] = Qs[(mb)     * AQS + ks * 8 + c + 4];
            af[3] = Qs[(mb + 8) * AQS + ks * 8 + c + 4];
            #pragma unroll
            for (int nt = 0; nt < 8; nt++) {
                bf[nt][0] = Ks[(nt * 8 + g) * AQS + ks * 8 + c];
                bf[nt][1] = Ks[(nt * 8 + g) * AQS + ks * 8 + c + 4];
            }
            #pragma unroll
            for (int nt = 0; nt < 8; nt++)
                mma_tf32(s[nt], af, bf[nt]);
        }

        if (kb + ABK > TOTALT) {
            #pragma unroll
            for (int nt = 0; nt < 8; nt++) {
                int j0 = kb + nt * 8 + 2 * c;
                if (j0     >= TOTALT) { s[nt][0] = -1e30f; s[nt][2] = -1e30f; }
                if (j0 + 1 >= TOTALT) { s[nt][1] = -1e30f; s[nt][3] = -1e30f; }
            }
        }

        float tmax0 = -1e30f, tmax1 = -1e30f;
        #pragma unroll
        for (int nt = 0; nt < 8; nt++) {
            tmax0 = fmaxf(tmax0, fmaxf(s[nt][0], s[nt][1]));
            tmax1 = fmaxf(tmax1, fmaxf(s[nt][2], s[nt][3]));
        }
        tmax0 = fmaxf(tmax0, __shfl_xor_sync(0xffffffffu, tmax0, 1));
        tmax0 = fmaxf(tmax0, __shfl_xor_sync(0xffffffffu, tmax0, 2));
        tmax1 = fmaxf(tmax1, __shfl_xor_sync(0xffffffffu, tmax1, 1));
        tmax1 = fmaxf(tmax1, __shfl_xor_sync(0xffffffffu, tmax1, 2));
        float mn0 = fmaxf(m0, tmax0), mn1 = fmaxf(m1, tmax1);
        float a0 = __expf(m0 - mn0), a1 = __expf(m1 - mn1);
        m0 = mn0; m1 = mn1;

        float ps0 = 0.f, ps1 = 0.f;
        #pragma unroll
        for (int nt = 0; nt < 8; nt++) {
            s[nt][0] = __expf(s[nt][0] - mn0);
            s[nt][1] = __expf(s[nt][1] - mn0);
            s[nt][2] = __expf(s[nt][2] - mn1);
            s[nt][3] = __expf(s[nt][3] - mn1);
            ps0 += s[nt][0] + s[nt][1];
            ps1 += s[nt][2] + s[nt][3];
        }
        ps0 += __shfl_xor_sync(0xffffffffu, ps0, 1);
        ps0 += __shfl_xor_sync(0xffffffffu, ps0, 2);
        ps1 += __shfl_xor_sync(0xffffffffu, ps1, 1);
        ps1 += __shfl_xor_sync(0xffffffffu, ps1, 2);
        l0 = l0 * a0 + ps0;
        l1 = l1 * a1 + ps1;
        #pragma unroll
        for (int nt = 0; nt < 16; nt++) {
            o[nt][0] *= a0; o[nt][1] *= a0;
            o[nt][2] *= a1; o[nt][3] *= a1;
        }

        #pragma unroll
        for (int nt = 0; nt < 8; nt++) {
            *(uint2*)(Ps + (wr16 + g)     * AVS + nt * 8 + 2 * c) =
                make_uint2(f2tf32(s[nt][0]), f2tf32(s[nt][1]));
            *(uint2*)(Ps + (wr16 + g + 8) * AVS + nt * 8 + 2 * c) =
                make_uint2(f2tf32(s[nt][2]), f2tf32(s[nt][3]));
        }
        __syncwarp();

        #pragma unroll
        for (int ks2 = 0; ks2 < 8; ks2++) {
            unsigned af[4];
            af[0] = Ps[(wr16 + g)     * AVS + ks2 * 8 + c];
            af[1] = Ps[(wr16 + g + 8) * AVS + ks2 * 8 + c];
            af[2] = Ps[(wr16 + g)     * AVS + ks2 * 8 + c + 4];
            af[3] = Ps[(wr16 + g + 8) * AVS + ks2 * 8 + c + 4];
            #pragma unroll
            for (int nt2 = 0; nt2 < 16; nt2++) {
                unsigned bf[2];
                bf[0] = Vt[(nt2 * 8 + g) * AVS + ks2 * 8 + c];
                bf[1] = Vt[(nt2 * 8 + g) * AVS + ks2 * 8 + c + 4];
                mma_tf32(o[nt2], af, bf);
            }
        }
    }

    // epilogue: store tf32-rounded (feeds proj GEMMs which need rounded input)
    float inv0 = 1.f / l0, inv1 = 1.f / l1;
    int r0 = i0 + wr16 + g, r1 = r0 + 8;
    if (r0 < TOTALT) {
        int dst = vidx[r0];
        float* orow = full + (size_t)dst * DXC + h * DD;
        #pragma unroll
        for (int nt2 = 0; nt2 < 16; nt2++)
            *(uint2*)(orow + nt2 * 8 + 2 * c) =
                make_uint2(f2tf32(o[nt2][0] * inv0), f2tf32(o[nt2][1] * inv0));
    }
    if (r1 < TOTALT) {
        int dst = vidx[r1];
        float* orow = full + (size_t)dst * DXC + h * DD;
        #pragma unroll
        for (int nt2 = 0; nt2 < 16; nt2++)
            *(uint2*)(orow + nt2 * 8 + 2 * c) =
                make_uint2(f2tf32(o[nt2][2] * inv1), f2tf32(o[nt2][3] * inv1));
    }
}

// ---------------- driver ----------------------------------------------------
extern "C" void kernel_launch(void* const* d_in, const int* in_sizes, int n_in,
                              void* d_out, int out_size) {
    const float* x       = (const float*)d_in[0];
    const float* y       = (const float*)d_in[1];
    const float* scale_x = (const float*)d_in[2];
    const float* scale_y = (const float*)d_in[3];
    const float* rcos    = (const float*)d_in[4];
    const float* rsin    = (const float*)d_in[5];
    const float* Wqkvx   = (const float*)d_in[6];
    const float* bqkvx   = (const float*)d_in[7];
    const float* Wqkvy   = (const float*)d_in[8];
    const float* bqkvy   = (const float*)d_in[9];
    const float* qnx     = (const float*)d_in[10];
    const float* knx     = (const float*)d_in[11];
    const float* qny     = (const float*)d_in[12];
    const float* kny     = (const float*)d_in[13];
    const float* Wpx     = (const float*)d_in[14];
    const float* bpx     = (const float*)d_in[15];
    const float* Wpy     = (const float*)d_in[16];
    const float* bpy     = (const float*)d_in[17];
    const int*   vidx    = (const int*)d_in[18];
    float* out = (float*)d_out;

    float *xm, *ym, *qkvx, *qkvy, *q, *k, *v, *full, *wqx, *wqy, *wpx, *wpy;
    cudaGetSymbolAddress((void**)&xm,   g_xm);
    cudaGetSymbolAddress((void**)&ym,   g_ym);
    cudaGetSymbolAddress((void**)&qkvx, g_qkvx);
    cudaGetSymbolAddress((void**)&qkvy, g_qkvy);
    cudaGetSymbolAddress((void**)&q,    g_q);
    cudaGetSymbolAddress((void**)&k,    g_k);
    cudaGetSymbolAddress((void**)&v,    g_v);
    cudaGetSymbolAddress((void**)&full, g_full);
    cudaGetSymbolAddress((void**)&wqx,  g_wqx);
    cudaGetSymbolAddress((void**)&wqy,  g_wqy);
    cudaGetSymbolAddress((void**)&wpx,  g_wpx);
    cudaGetSymbolAddress((void**)&wpy,  g_wpy);

    // 0. pre-round all weights to tf32 — single fused float4 launch
    round4_kernel<<<4096, 256>>>(
        (const float4*)Wqkvx, (float4*)wqx, (3 * DXC * DXC) / 4,
        (const float4*)Wqkvy, (float4*)wqy, (3 * DXC * DYC) / 4,
        (const float4*)Wpx,   (float4*)wpx, (DXC * DXC) / 4,
        (const float4*)Wpy,   (float4*)wpy, (DYC * DXC) / 4);

    // 1. input rmsnorm + modulation (tf32-rounded outputs); zero only the
    //    tail rows of `full` (attention fully overwrites rows 0..TOTALT-1)
    rmsnorm_mod_kernel<<<NX, 256>>>(x, scale_x, xm, DXC);
    rmsnorm_mod_kernel<<<LY, 256>>>(y, scale_y, ym, DYC);
    zero_kernel<<<64, 256>>>(full + (size_t)TOTALT * DXC, (NX + LY - TOTALT) * DXC);

    // 2. qkv projections — x and y fused in one launch
    cudaFuncSetAttribute(gemm_dual, cudaFuncAttributeMaxDynamicSharedMemorySize, DS_SMEM);
    {
        const int nbx = (NX / 128) * (QKVC / 256);   // 576
        const int nby = (LY / 128) * (QKVC / 256);   // 72
        gemm_dual<<<nbx + nby, 256, DS_SMEM>>>(
            xm, wqx, bqkvx, qkvx, QKVC, DXC,
            ym, wqy, bqkvy, qkvy, QKVC, DYC,
            nbx, QKVC / 256, QKVC / 256);
    }

    // 3. per-head norm + rope, gather valid tokens into [H][TOTAL][D]
    qkv_post_kernel<<<dim3(TOTALT, HH), 128>>>(qkvx, qkvy, rcos, rsin,
                                               qnx, knx, qny, kny, vidx, q, k, v);

    // 4. attention (TF32 tensor cores) -> scatter into full (tf32-rounded)
    const int ATTN_SMEM = (ABQ * AQS + ABK * AQS + DD * AVS + ABQ * AVS) * 4;  // 171008 B
    cudaFuncSetAttribute(attn_mma_kernel, cudaFuncAttributeMaxDynamicSharedMemorySize, ATTN_SMEM);
    attn_mma_kernel<<<dim3((TOTALT + ABQ - 1) / ABQ, HH), 256, ATTN_SMEM>>>(q, k, v, vidx, full);

    // 5. output projections — x and y fused in one launch
    {
        const int nbx = (NX / 128) * (DXC / 256);    // 192
        const int nby = (LY / 128) * (DYC / 256);    // 12
        gemm_dual<<<nbx + nby, 256, DS_SMEM>>>(
            full, wpx, bpx, out, DXC, DXC,
            full + (size_t)NX * DXC, wpy, bpy, out + (size_t)NX * DXC, DYC, DXC,
            nbx, DXC / 256, DYC / 256);
    }
}

// round 17
// speedup vs baseline: 3.7276x; 1.0810x over previous
#include <cuda_runtime.h>
#include <cstddef>
#include <cstdint>

#define NX    2048
#define LY    256
#define HH    24
#define DD    128
#define DXC   3072
#define DYC   1536
#define QKVC  9216
#define TOTALT 2248

// ---------------- scratch (static device globals; no allocation) ------------
__device__ float g_xm  [(size_t)NX * DXC];
__device__ float g_ym  [(size_t)LY * DYC];
__device__ float g_qkvx[(size_t)NX * QKVC];
__device__ float g_qkvy[(size_t)LY * QKVC];
__device__ float g_q   [(size_t)HH * TOTALT * DD];
__device__ float g_k   [(size_t)HH * TOTALT * DD];
__device__ float g_v   [(size_t)HH * TOTALT * DD];
__device__ float g_full[(size_t)(NX + LY) * DXC];
__device__ float g_wqx [(size_t)3 * DXC * DXC];   // tf32-rounded weights
__device__ float g_wqy [(size_t)3 * DXC * DYC];
__device__ float g_wpx [(size_t)DXC * DXC];
__device__ float g_wpy [(size_t)DYC * DXC];

// ---------------- helpers ----------------------------------------------------
__device__ __forceinline__ unsigned f2tf32(float f) {
    unsigned r;
    asm("cvt.rna.tf32.f32 %0, %1;" : "=r"(r) : "f"(f));
    return r;
}

__device__ __forceinline__ void mma_tf32(float* d, const unsigned* a, const unsigned* b) {
    asm volatile(
        "mma.sync.aligned.m16n8k8.row.col.f32.tf32.tf32.f32 "
        "{%0,%1,%2,%3}, {%4,%5,%6,%7}, {%8,%9}, {%0,%1,%2,%3};\n"
        : "+f"(d[0]), "+f"(d[1]), "+f"(d[2]), "+f"(d[3])
        : "r"(a[0]), "r"(a[1]), "r"(a[2]), "r"(a[3]), "r"(b[0]), "r"(b[1]));
}

__device__ __forceinline__ void cpasync16(void* dst, const void* src) {
    unsigned d = (unsigned)__cvta_generic_to_shared(dst);
    asm volatile("cp.async.cg.shared.global [%0], [%1], 16;" :: "r"(d), "l"(src));
}
__device__ __forceinline__ void cp_commit() {
    asm volatile("cp.async.commit_group;");
}
template <int N_>
__device__ __forceinline__ void cp_wait() {
    asm volatile("cp.async.wait_group %0;" :: "n"(N_));
}

// ---------------- fused tf32 rounding pass (all 4 weight tensors) ------------
__global__ void round4_kernel(const float4* __restrict__ i0, float4* __restrict__ o0, int n0,
                              const float4* __restrict__ i1, float4* __restrict__ o1, int n1,
                              const float4* __restrict__ i2, float4* __restrict__ o2, int n2,
                              const float4* __restrict__ i3, float4* __restrict__ o3, int n3) {
    const int total = n0 + n1 + n2 + n3;
    for (int i = blockIdx.x * blockDim.x + threadIdx.x; i < total; i += gridDim.x * blockDim.x) {
        const float4* src;
        float4* dst;
        int j = i;
        if (j < n0) { src = i0; dst = o0; }
        else if ((j -= n0) < n1) { src = i1; dst = o1; }
        else if ((j -= n1) < n2) { src = i2; dst = o2; }
        else { j -= n2; src = i3; dst = o3; }
        float4 v = src[j];
        v.x = __uint_as_float(f2tf32(v.x));
        v.y = __uint_as_float(f2tf32(v.y));
        v.z = __uint_as_float(f2tf32(v.z));
        v.w = __uint_as_float(f2tf32(v.w));
        dst[j] = v;
    }
}

// ---------------- rmsnorm * (1 + scale), tf32-rounded output -----------------
__global__ void rmsnorm_mod_kernel(const float* __restrict__ x,
                                   const float* __restrict__ scale,
                                   float* __restrict__ out, int C) {
    int row = blockIdx.x;
    const float* xr = x + (size_t)row * C;
    float ss = 0.f;
    for (int c = threadIdx.x; c < C; c += blockDim.x) { float v = xr[c]; ss += v * v; }
    __shared__ float wsum[8];
    #pragma unroll
    for (int o = 16; o > 0; o >>= 1) ss += __shfl_xor_sync(0xffffffffu, ss, o);
    if ((threadIdx.x & 31) == 0) wsum[threadIdx.x >> 5] = ss;
    __syncthreads();
    float tot = 0.f;
    #pragma unroll
    for (int i = 0; i < 8; i++) tot += wsum[i];
    float r = rsqrtf(tot / (float)C + 1e-6f);
    float* orow = out + (size_t)row * C;
    for (int c = threadIdx.x; c < C; c += blockDim.x)
        orow[c] = __uint_as_float(f2tf32(xr[c] * r * (1.f + scale[c])));
}

// ---------------- zero fill --------------------------------------------------
__global__ void zero_kernel(float* __restrict__ p, int n) {
    for (int i = blockIdx.x * blockDim.x + threadIdx.x; i < n; i += gridDim.x * blockDim.x)
        p[i] = 0.f;
}

// ---------------- dual-part TF32 NT GEMM, 128x256 tiles, BK=64, 2-stage ------
// L2-aware CTA swizzle: bids walk gm m-tiles x all n-tiles per supertile group,
// shrinking per-wave W footprint below L2 capacity.
#define DS_ROW  68
#define DS_A    (128 * DS_ROW)
#define DS_B    (256 * DS_ROW)
#define DS_STG  (DS_A + DS_B)
#define DS_SMEM (2 * DS_STG * 4)     // 208896 B

__global__ void __launch_bounds__(256)
gemm_dual(const float* __restrict__ Ax, const float* __restrict__ Wx,
          const float* __restrict__ bx, float* __restrict__ Cx,
          int Nx_, int Kx_,
          const float* __restrict__ Ay, const float* __restrict__ Wy,
          const float* __restrict__ by, float* __restrict__ Cy,
          int Ny_, int Ky_,
          int nbx, int nnx, int nny, int gmx, int gmy) {
    extern __shared__ float sm[];
    const int tid  = threadIdx.x;
    const int lane = tid & 31;
    const int warp = tid >> 5;
    const int g    = lane >> 2;
    const int c    = lane & 3;
    const int wm   = warp >> 2;
    const int wn   = warp & 3;

    const float *A, *W, *bias;
    float* C;
    int N, K, m0, n0;
    const int bid = blockIdx.x;
    if (bid < nbx) {
        A = Ax; W = Wx; bias = bx; C = Cx; N = Nx_; K = Kx_;
        int grp = bid / (gmx * nnx), rem = bid % (gmx * nnx);
        m0 = (grp * gmx + rem % gmx) * 128;
        n0 = (rem / gmx) * 256;
    } else {
        int b = bid - nbx;
        A = Ay; W = Wy; bias = by; C = Cy; N = Ny_; K = Ky_;
        int grp = b / (gmy * nny), rem = b % (gmy * nny);
        m0 = (grp * gmy + rem % gmy) * 128;
        n0 = (rem / gmy) * 256;
    }

    float acc[4][8][4];
    #pragma unroll
    for (int mt = 0; mt < 4; mt++)
        #pragma unroll
        for (int nt = 0; nt < 8; nt++)
            #pragma unroll
            for (int r = 0; r < 4; r++) acc[mt][nt][r] = 0.f;

    const int niter = K / 64;

    auto load_stage = [&](int s, int k0) {
        float* as = sm + s * DS_STG;
        float* bs = as + DS_A;
        #pragma unroll
        for (int r = 0; r < 8; r++) {
            int idx = tid + r * 256;
            int row = idx >> 4, c4 = (idx & 15) << 2;
            cpasync16(as + row * DS_ROW + c4, A + (size_t)(m0 + row) * K + k0 + c4);
        }
        #pragma unroll
        for (int r = 0; r < 16; r++) {
            int idx = tid + r * 256;
            int row = idx >> 4, c4 = (idx & 15) << 2;
            cpasync16(bs + row * DS_ROW + c4, W + (size_t)(n0 + row) * K + k0 + c4);
        }
    };

    load_stage(0, 0);  cp_commit();
    load_stage(1, 64); cp_commit();

    for (int it = 0; it < niter; it++) {
        cp_wait<1>();
        __syncthreads();

        const float* as = sm + (it & 1) * DS_STG;
        const float* bs = as + DS_A;
        #pragma unroll
        for (int ks = 0; ks < 8; ks++) {
            unsigned af[4][4], bf[8][2];
            #pragma unroll
            for (int mt = 0; mt < 4; mt++) {
                int mb = wm * 64 + mt * 16 + g;
                af[mt][0] = __float_as_uint(as[(mb)     * DS_ROW + ks * 8 + c]);
                af[mt][1] = __float_as_uint(as[(mb + 8) * DS_ROW + ks * 8 + c]);
                af[mt][2] = __float_as_uint(as[(mb)     * DS_ROW + ks * 8 + c + 4]);
                af[mt][3] = __float_as_uint(as[(mb + 8) * DS_ROW + ks * 8 + c + 4]);
            }
            #pragma unroll
            for (int nt = 0; nt < 8; nt++) {
                int nb = wn * 64 + nt * 8 + g;
                bf[nt][0] = __float_as_uint(bs[nb * DS_ROW + ks * 8 + c]);
                bf[nt][1] = __float_as_uint(bs[nb * DS_ROW + ks * 8 + c + 4]);
            }
            #pragma unroll
            for (int mt = 0; mt < 4; mt++)
                #pragma unroll
                for (int nt = 0; nt < 8; nt++)
                    mma_tf32(acc[mt][nt], af[mt], bf[nt]);
        }
        __syncthreads();
        if (it + 2 < niter) load_stage(it & 1, (it + 2) * 64);
        cp_commit();
    }

    #pragma unroll
    for (int mt = 0; mt < 4; mt++) {
        int row = m0 + wm * 64 + mt * 16 + g;
        #pragma unroll
        for (int nt = 0; nt < 8; nt++) {
            int col = n0 + wn * 64 + nt * 8 + 2 * c;
            float b0 = bias[col], b1 = bias[col + 1];
            float2 v0 = make_float2(acc[mt][nt][0] + b0, acc[mt][nt][1] + b1);
            float2 v1 = make_float2(acc[mt][nt][2] + b0, acc[mt][nt][3] + b1);
            *(float2*)(C + (size_t)row * N + col)       = v0;
            *(float2*)(C + (size_t)(row + 8) * N + col) = v1;
        }
    }
}

// ---------------- per-(token,head) norm + rope -> q/k/v [H][TOTAL][D] -------
// Outputs tf32-rounded; q pre-scaled by 1/sqrt(D). Attention loaders then
// store raw bits (no cvt) and can use cp.async.
__global__ void qkv_post_kernel(const float* __restrict__ qkvx, const float* __restrict__ qkvy,
                                const float* __restrict__ rcos, const float* __restrict__ rsin,
                                const float* __restrict__ qnx,  const float* __restrict__ knx,
                                const float* __restrict__ qny,  const float* __restrict__ kny,
                                const int* __restrict__ vidx,
                                float* __restrict__ qo, float* __restrict__ ko,
                                float* __restrict__ vo) {
    int i = blockIdx.x, h = blockIdx.y, d = threadIdx.x;
    const float qscale = 0.08838834764831845f;  // 1/sqrt(128)
    int src = vidx[i];
    bool isx = src < NX;
    const float* base = isx ? (qkvx + (size_t)src * QKVC)
                            : (qkvy + (size_t)(src - NX) * QKVC);
    float qv = base[h * DD + d];
    float kv = base[DXC + h * DD + d];
    float vv = base[2 * DXC + h * DD + d];

    float qs = qv * qv, ks = kv * kv;
    #pragma unroll
    for (int o = 16; o > 0; o >>= 1) {
        qs += __shfl_xor_sync(0xffffffffu, qs, o);
        ks += __shfl_xor_sync(0xffffffffu, ks, o);
    }
    __shared__ float sq[4], sk[4];
    __shared__ float qsh[DD], ksh[DD];
    int wid = d >> 5;
    if ((d & 31) == 0) { sq[wid] = qs; sk[wid] = ks; }
    __syncthreads();
    float qss = sq[0] + sq[1] + sq[2] + sq[3];
    float kss = sk[0] + sk[1] + sk[2] + sk[3];
    float qn = qv * rsqrtf(qss / (float)DD + 1e-6f) * (isx ? qnx[d] : qny[d]);
    float kn = kv * rsqrtf(kss / (float)DD + 1e-6f) * (isx ? knx[d] : kny[d]);

    if (isx) {
        qsh[d] = qn; ksh[d] = kn;
        __syncthreads();
        int j = d >> 1;
        float cc = rcos[((size_t)src * HH + h) * 64 + j];
        float sn = rsin[((size_t)src * HH + h) * 64 + j];
        if ((d & 1) == 0) {
            qn = qsh[d] * cc - qsh[d + 1] * sn;
            kn = ksh[d] * cc - ksh[d + 1] * sn;
        } else {
            qn = qsh[d - 1] * sn + qsh[d] * cc;
            kn = ksh[d - 1] * sn + ksh[d] * cc;
        }
    }
    size_t o = ((size_t)h * TOTALT + i) * DD + d;
    qo[o] = __uint_as_float(f2tf32(qn * qscale));
    ko[o] = __uint_as_float(f2tf32(kn));
    vo[o] = __uint_as_float(f2tf32(vv));
}

// ---------------- TF32 tensor-core flash attention ---------------------------
// Inputs pre-rounded (q pre-scaled). Q/K tiles loaded via cp.async (no cvt,
// no register round-trip); V transposed in-kernel storing raw bits.
#define AQS 132
#define AVS 68
#define ABQ 128
#define ABK 64

__global__ void __launch_bounds__(256)
attn_mma_kernel(const float* __restrict__ qg, const float* __restrict__ kg,
                const float* __restrict__ vg, const int* __restrict__ vidx,
                float* __restrict__ full) {
    extern __shared__ unsigned asm_[];
    unsigned* Qs = asm_;                    // 128*132
    unsigned* Ks = Qs + ABQ * AQS;          // 64*132
    unsigned* Vt = Ks + ABK * AQS;          // 128*68
    unsigned* Ps = Vt + DD * AVS;           // 128*68

    const int h    = blockIdx.y;
    const int i0   = blockIdx.x * ABQ;
    const int tid  = threadIdx.x;
    const int lane = tid & 31;
    const int warp = tid >> 5;
    const int g    = lane >> 2;
    const int c    = lane & 3;
    const int q4   = lane >> 2;
    const int wr16 = warp * 16;

    const float* qh = qg + (size_t)h * TOTALT * DD;
    const float* kh = kg + (size_t)h * TOTALT * DD;
    const float* vh = vg + (size_t)h * TOTALT * DD;

    // ---- Q tile via cp.async (pre-rounded, pre-scaled) ----
    #pragma unroll
    for (int it = 0; it < 16; it++) {
        int f = tid + it * 256;
        int row = f >> 5, c4 = (f & 31) << 2;
        int qi = i0 + row; if (qi >= TOTALT) qi = TOTALT - 1;
        cpasync16(Qs + row * AQS + c4, qh + (size_t)qi * DD + c4);
    }
    cp_commit();

    float o[16][4];
    #pragma unroll
    for (int nt = 0; nt < 16; nt++)
        #pragma unroll
        for (int r = 0; r < 4; r++) o[nt][r] = 0.f;
    float m0 = -1e30f, m1 = -1e30f, l0 = 0.f, l1 = 0.f;

    const int ntiles = (TOTALT + ABK - 1) / ABK;
    for (int t = 0; t < ntiles; t++) {
        const int kb = t * ABK;
        __syncthreads();
        // ---- K tile via cp.async ----
        #pragma unroll
        for (int it = 0; it < 8; it++) {
            int f = tid + it * 256;
            int row = f >> 5, c4 = (f & 31) << 2;
            int kidx = kb + row; if (kidx >= TOTALT) kidx = TOTALT - 1;
            cpasync16(Ks + row * AQS + c4, kh + (size_t)kidx * DD + c4);
        }
        cp_commit();
        // ---- V tile transposed (raw bits, rotated scatter) ----
        #pragma unroll
        for (int it = 0; it < 8; it++) {
            int ci = it * 8 + warp;
            int rg = ci & 15;
            int cc = ci >> 4;
            int jb = rg * 4;
            int d0 = cc * 32 + q4 * 4;
            int jrow = kb + jb + c; if (jrow >= TOTALT) jrow = TOTALT - 1;
            float4 tv = *(const float4*)(vh + (size_t)jrow * DD + d0);
            const float* tp = &tv.x;
            #pragma unroll
            for (int ii = 0; ii < 4; ii++) {
                int i = (ii + q4) & 3;
                Vt[(d0 + i) * AVS + jb + c] = __float_as_uint(tp[i]);
            }
        }
        cp_wait<0>();
        __syncthreads();

        // ---- S = Q K^T (scale pre-folded into Q) ----
        float s[8][4];
        #pragma unroll
        for (int nt = 0; nt < 8; nt++)
            #pragma unroll
            for (int r = 0; r < 4; r++) s[nt][r] = 0.f;
        #pragma unroll
        for (int ks = 0; ks < 16; ks++) {
            unsigned af[4], bf[8][2];
            int mb = wr16 + g;
            af[0] = Qs[(mb)     * AQS + ks * 8 + c];
            af[1] = Qs[(mb + 8) * AQS + ks * 8 + c];
            af[2] = Qs[(mb)     * AQS + ks * 8 + c + 4];
            af[3] = Qs[(mb + 8) * AQS + ks * 8 + c + 4];
            #pragma unroll
            for (int nt = 0; nt < 8; nt++) {
                bf[nt][0] = Ks[(nt * 8 + g) * AQS + ks * 8 + c];
                bf[nt][1] = Ks[(nt * 8 + g) * AQS + ks * 8 + c + 4];
            }
            #pragma unroll
            for (int nt = 0; nt < 8; nt++)
                mma_tf32(s[nt], af, bf[nt]);
        }

        if (kb + ABK > TOTALT) {
            #pragma unroll
            for (int nt = 0; nt < 8; nt++) {
                int j0 = kb + nt * 8 + 2 * c;
                if (j0     >= TOTALT) { s[nt][0] = -1e30f; s[nt][2] = -1e30f; }
                if (j0 + 1 >= TOTALT) { s[nt][1] = -1e30f; s[nt][3] = -1e30f; }
            }
        }

        float tmax0 = -1e30f, tmax1 = -1e30f;
        #pragma unroll
        for (int nt = 0; nt < 8; nt++) {
            tmax0 = fmaxf(tmax0, fmaxf(s[nt][0], s[nt][1]));
            tmax1 = fmaxf(tmax1, fmaxf(s[nt][2], s[nt][3]));
        }
        tmax0 = fmaxf(tmax0, __shfl_xor_sync(0xffffffffu, tmax0, 1));
        tmax0 = fmaxf(tmax0, __shfl_xor_sync(0xffffffffu, tmax0, 2));
        tmax1 = fmaxf(tmax1, __shfl_xor_sync(0xffffffffu, tmax1, 1));
        tmax1 = fmaxf(tmax1, __shfl_xor_sync(0xffffffffu, tmax1, 2));
        float mn0 = fmaxf(m0, tmax0), mn1 = fmaxf(m1, tmax1);
        float a0 = __expf(m0 - mn0), a1 = __expf(m1 - mn1);
        m0 = mn0; m1 = mn1;

        float ps0 = 0.f, ps1 = 0.f;
        #pragma unroll
        for (int nt = 0; nt < 8; nt++) {
            s[nt][0] = __expf(s[nt][0] - mn0);
            s[nt][1] = __expf(s[nt][1] - mn0);
            s[nt][2] = __expf(s[nt][2] - mn1);
            s[nt][3] = __expf(s[nt][3] - mn1);
            ps0 += s[nt][0] + s[nt][1];
            ps1 += s[nt][2] + s[nt][3];
        }
        ps0 += __shfl_xor_sync(0xffffffffu, ps0, 1);
        ps0 += __shfl_xor_sync(0xffffffffu, ps0, 2);
        ps1 += __shfl_xor_sync(0xffffffffu, ps1, 1);
        ps1 += __shfl_xor_sync(0xffffffffu, ps1, 2);
        l0 = l0 * a0 + ps0;
        l1 = l1 * a1 + ps1;
        #pragma unroll
        for (int nt = 0; nt < 16; nt++) {
            o[nt][0] *= a0; o[nt][1] *= a0;
            o[nt][2] *= a1; o[nt][3] *= a1;
        }

        #pragma unroll
        for (int nt = 0; nt < 8; nt++) {
            *(uint2*)(Ps + (wr16 + g)     * AVS + nt * 8 + 2 * c) =
                make_uint2(f2tf32(s[nt][0]), f2tf32(s[nt][1]));
            *(uint2*)(Ps + (wr16 + g + 8) * AVS + nt * 8 + 2 * c) =
                make_uint2(f2tf32(s[nt][2]), f2tf32(s[nt][3]));
        }
        __syncwarp();

        #pragma unroll
        for (int ks2 = 0; ks2 < 8; ks2++) {
            unsigned af[4];
            af[0] = Ps[(wr16 + g)     * AVS + ks2 * 8 + c];
            af[1] = Ps[(wr16 + g + 8) * AVS + ks2 * 8 + c];
            af[2] = Ps[(wr16 + g)     * AVS + ks2 * 8 + c + 4];
            af[3] = Ps[(wr16 + g + 8) * AVS + ks2 * 8 + c + 4];
            #pragma unroll
            for (int nt2 = 0; nt2 < 16; nt2++) {
                unsigned bf[2];
                bf[0] = Vt[(nt2 * 8 + g) * AVS + ks2 * 8 + c];
                bf[1] = Vt[(nt2 * 8 + g) * AVS + ks2 * 8 + c + 4];
                mma_tf32(o[nt2], af, bf);
            }
        }
    }

    // epilogue: store tf32-rounded (feeds proj GEMMs)
    float inv0 = 1.f / l0, inv1 = 1.f / l1;
    int r0 = i0 + wr16 + g, r1 = r0 + 8;
    if (r0 < TOTALT) {
        int dst = vidx[r0];
        float* orow = full + (size_t)dst * DXC + h * DD;
        #pragma unroll
        for (int nt2 = 0; nt2 < 16; nt2++)
            *(uint2*)(orow + nt2 * 8 + 2 * c) =
                make_uint2(f2tf32(o[nt2][0] * inv0), f2tf32(o[nt2][1] * inv0));
    }
    if (r1 < TOTALT) {
        int dst = vidx[r1];
        float* orow = full + (size_t)dst * DXC + h * DD;
        #pragma unroll
        for (int nt2 = 0; nt2 < 16; nt2++)
            *(uint2*)(orow + nt2 * 8 + 2 * c) =
                make_uint2(f2tf32(o[nt2][2] * inv1), f2tf32(o[nt2][3] * inv1));
    }
}

// ---------------- driver ----------------------------------------------------
extern "C" void kernel_launch(void* const* d_in, const int* in_sizes, int n_in,
                              void* d_out, int out_size) {
    const float* x       = (const float*)d_in[0];
    const float* y       = (const float*)d_in[1];
    const float* scale_x = (const float*)d_in[2];
    const float* scale_y = (const float*)d_in[3];
    const float* rcos    = (const float*)d_in[4];
    const float* rsin    = (const float*)d_in[5];
    const float* Wqkvx   = (const float*)d_in[6];
    const float* bqkvx   = (const float*)d_in[7];
    const float* Wqkvy   = (const float*)d_in[8];
    const float* bqkvy   = (const float*)d_in[9];
    const float* qnx     = (const float*)d_in[10];
    const float* knx     = (const float*)d_in[11];
    const float* qny     = (const float*)d_in[12];
    const float* kny     = (const float*)d_in[13];
    const float* Wpx     = (const float*)d_in[14];
    const float* bpx     = (const float*)d_in[15];
    const float* Wpy     = (const float*)d_in[16];
    const float* bpy     = (const float*)d_in[17];
    const int*   vidx    = (const int*)d_in[18];
    float* out = (float*)d_out;

    float *xm, *ym, *qkvx, *qkvy, *q, *k, *v, *full, *wqx, *wqy, *wpx, *wpy;
    cudaGetSymbolAddress((void**)&xm,   g_xm);
    cudaGetSymbolAddress((void**)&ym,   g_ym);
    cudaGetSymbolAddress((void**)&qkvx, g_qkvx);
    cudaGetSymbolAddress((void**)&qkvy, g_qkvy);
    cudaGetSymbolAddress((void**)&q,    g_q);
    cudaGetSymbolAddress((void**)&k,    g_k);
    cudaGetSymbolAddress((void**)&v,    g_v);
    cudaGetSymbolAddress((void**)&full, g_full);
    cudaGetSymbolAddress((void**)&wqx,  g_wqx);
    cudaGetSymbolAddress((void**)&wqy,  g_wqy);
    cudaGetSymbolAddress((void**)&wpx,  g_wpx);
    cudaGetSymbolAddress((void**)&wpy,  g_wpy);

    // 0. pre-round all weights to tf32 — single fused float4 launch
    round4_kernel<<<4096, 256>>>(
        (const float4*)Wqkvx, (float4*)wqx, (3 * DXC * DXC) / 4,
        (const float4*)Wqkvy, (float4*)wqy, (3 * DXC * DYC) / 4,
        (const float4*)Wpx,   (float4*)wpx, (DXC * DXC) / 4,
        (const float4*)Wpy,   (float4*)wpy, (DYC * DXC) / 4);

    // 1. input rmsnorm + modulation; zero only the tail rows of `full`
    rmsnorm_mod_kernel<<<NX, 256>>>(x, scale_x, xm, DXC);
    rmsnorm_mod_kernel<<<LY, 256>>>(y, scale_y, ym, DYC);
    zero_kernel<<<64, 256>>>(full + (size_t)TOTALT * DXC, (NX + LY - TOTALT) * DXC);

    // 2. qkv projections — x and y fused in one launch, L2-swizzled
    cudaFuncSetAttribute(gemm_dual, cudaFuncAttributeMaxDynamicSharedMemorySize, DS_SMEM);
    {
        const int nbx = (NX / 128) * (QKVC / 256);   // 576
        const int nby = (LY / 128) * (QKVC / 256);   // 72
        gemm_dual<<<nbx + nby, 256, DS_SMEM>>>(
            xm, wqx, bqkvx, qkvx, QKVC, DXC,
            ym, wqy, bqkvy, qkvy, QKVC, DYC,
            nbx, QKVC / 256, QKVC / 256, 8, 2);
    }

    // 3. per-head norm + rope (tf32-rounded, q pre-scaled)
    qkv_post_kernel<<<dim3(TOTALT, HH), 128>>>(qkvx, qkvy, rcos, rsin,
                                               qnx, knx, qny, kny, vidx, q, k, v);

    // 4. attention -> scatter into full (tf32-rounded)
    const int ATTN_SMEM = (ABQ * AQS + ABK * AQS + DD * AVS + ABQ * AVS) * 4;  // 171008 B
    cudaFuncSetAttribute(attn_mma_kernel, cudaFuncAttributeMaxDynamicSharedMemorySize, ATTN_SMEM);
    attn_mma_kernel<<<dim3((TOTALT + ABQ - 1) / ABQ, HH), 256, ATTN_SMEM>>>(q, k, v, vidx, full);

    // 5. output projections — x and y fused in one launch, L2-swizzled
    {
        const int nbx = (NX / 128) * (DXC / 256);    // 192
        const int nby = (LY / 128) * (DYC / 256);    // 12
        gemm_dual<<<nbx + nby, 256, DS_SMEM>>>(
            full, wpx, bpx, out, DXC, DXC,
            full + (size_t)NX * DXC, wpy, bpy, out + (size_t)NX * DXC, DYC, DXC,
            nbx, DXC / 256, DYC / 256, 8, 2);
    }
}